// round 1
// baseline (speedup 1.0000x reference)
#include <cuda_runtime.h>
#include <cuda_bf16.h>
#include <math.h>

// ---------------------------------------------------------------------------
// TransformerBlock: B=2, S=2048, D=1024, H=16, Dk=64, D_FF=4096, fp32
// Pipeline:
//   1) q,k,v = x@W^T + b      (3x SGEMM, scatter to [B,H,S,Dk])
//   2) flash attention        -> ctx [B,S,D]
//   3) y = ctx@wo^T + bo + x  (SGEMM + residual)
//   4) attn = LN1(y)
//   5) h = GELU(attn@w1^T+b1) (SGEMM + gelu epilogue)
//   6) y = h@w2^T + b2 + attn (SGEMM + residual)
//   7) out = LN2(y)
// ---------------------------------------------------------------------------

#define D_MODEL 1024
#define NTOK    4096        // B*S
#define NHEAD   16
#define DK      64
#define DFF     4096
#define SEQ     2048
#define EPS     1e-5f

// ------------------------- scratch (static device mem) ---------------------
__device__ float g_q[NTOK * D_MODEL];
__device__ float g_k[NTOK * D_MODEL];
__device__ float g_v[NTOK * D_MODEL];
__device__ float g_ctx[NTOK * D_MODEL];
__device__ float g_y[NTOK * D_MODEL];
__device__ float g_attn[NTOK * D_MODEL];
__device__ float g_h[NTOK * DFF];

// ------------------------------ SGEMM --------------------------------------
// C[M,N] = A[M,K] @ W[N,K]^T + bias, with epilogue modes.
#define BM 128
#define BN 128
#define BK 16

#define MODE_QKV  1   // scatter to [B,H,S,Dk]
#define MODE_RES  2   // + residual[m,n]
#define MODE_GELU 3   // exact gelu

__device__ __forceinline__ float gelu_f(float x) {
    return 0.5f * x * (1.0f + erff(x * 0.70710678118654752f));
}

template <int MODE>
__global__ void __launch_bounds__(256, 2) sgemm_kernel(
    const float* __restrict__ A, const float* __restrict__ W,
    const float* __restrict__ bias, const float* __restrict__ res,
    float* __restrict__ C, int M, int N, int K)
{
    __shared__ float As[BK][BM + 4];
    __shared__ float Bs[BK][BN + 4];

    const int tid  = threadIdx.x;
    const int ty   = tid >> 4;          // 0..15
    const int tx   = tid & 15;          // 0..15
    const int brow = blockIdx.y * BM;
    const int bcol = blockIdx.x * BN;

    const float* Ap = A + (size_t)brow * K;
    const float* Wp = W + (size_t)bcol * K;

    const int r0 = tid >> 2;            // 0..63
    const int r1 = r0 + 64;             // 64..127
    const int c0 = (tid & 3) << 2;      // 0,4,8,12

    // prefetch tile 0 into registers
    float4 a0 = *(const float4*)(Ap + (size_t)r0 * K + c0);
    float4 a1 = *(const float4*)(Ap + (size_t)r1 * K + c0);
    float4 b0 = *(const float4*)(Wp + (size_t)r0 * K + c0);
    float4 b1 = *(const float4*)(Wp + (size_t)r1 * K + c0);

    float acc[8][8];
    #pragma unroll
    for (int i = 0; i < 8; i++)
        #pragma unroll
        for (int j = 0; j < 8; j++) acc[i][j] = 0.0f;

    const int T = K / BK;
    for (int t = 0; t < T; t++) {
        // regs -> smem (transposed)
        As[c0 + 0][r0] = a0.x; As[c0 + 1][r0] = a0.y; As[c0 + 2][r0] = a0.z; As[c0 + 3][r0] = a0.w;
        As[c0 + 0][r1] = a1.x; As[c0 + 1][r1] = a1.y; As[c0 + 2][r1] = a1.z; As[c0 + 3][r1] = a1.w;
        Bs[c0 + 0][r0] = b0.x; Bs[c0 + 1][r0] = b0.y; Bs[c0 + 2][r0] = b0.z; Bs[c0 + 3][r0] = b0.w;
        Bs[c0 + 0][r1] = b1.x; Bs[c0 + 1][r1] = b1.y; Bs[c0 + 2][r1] = b1.z; Bs[c0 + 3][r1] = b1.w;
        __syncthreads();

        if (t + 1 < T) {
            const int k0 = (t + 1) * BK;
            a0 = *(const float4*)(Ap + (size_t)r0 * K + k0 + c0);
            a1 = *(const float4*)(Ap + (size_t)r1 * K + k0 + c0);
            b0 = *(const float4*)(Wp + (size_t)r0 * K + k0 + c0);
            b1 = *(const float4*)(Wp + (size_t)r1 * K + k0 + c0);
        }

        #pragma unroll
        for (int k = 0; k < BK; k++) {
            float a[8], b[8];
            *(float4*)(a)     = *(const float4*)&As[k][ty * 8];
            *(float4*)(a + 4) = *(const float4*)&As[k][ty * 8 + 4];
            *(float4*)(b)     = *(const float4*)&Bs[k][tx * 8];
            *(float4*)(b + 4) = *(const float4*)&Bs[k][tx * 8 + 4];
            #pragma unroll
            for (int i = 0; i < 8; i++)
                #pragma unroll
                for (int j = 0; j < 8; j++)
                    acc[i][j] = fmaf(a[i], b[j], acc[i][j]);
        }
        __syncthreads();
    }

    // epilogue
    #pragma unroll
    for (int i = 0; i < 8; i++) {
        const int m = brow + ty * 8 + i;
        #pragma unroll
        for (int jj = 0; jj < 8; jj += 4) {
            const int n = bcol + tx * 8 + jj;
            float4 v;
            v.x = acc[i][jj + 0];
            v.y = acc[i][jj + 1];
            v.z = acc[i][jj + 2];
            v.w = acc[i][jj + 3];
            float4 bb = *(const float4*)(bias + n);
            v.x += bb.x; v.y += bb.y; v.z += bb.z; v.w += bb.w;
            if (MODE == MODE_RES) {
                float4 rr = *(const float4*)(res + (size_t)m * N + n);
                v.x += rr.x; v.y += rr.y; v.z += rr.z; v.w += rr.w;
            }
            if (MODE == MODE_GELU) {
                v.x = gelu_f(v.x); v.y = gelu_f(v.y);
                v.z = gelu_f(v.z); v.w = gelu_f(v.w);
            }
            if (MODE == MODE_QKV) {
                // m = token (b*2048+s), n = channel (h*64+d)
                const int bq = m >> 11, sq = m & 2047;
                const int hq = n >> 6,  dq = n & 63;
                float* o = C + ((size_t)(bq * NHEAD + hq) * SEQ + sq) * DK + dq;
                *(float4*)o = v;
            } else {
                *(float4*)(C + (size_t)m * N + n) = v;
            }
        }
    }
}

// -------------------------- flash attention --------------------------------
// Q,K,V: [B*H, S, 64].  ctx: [B, S, 1024].
// CTA: 256 threads = 64 query rows x 4 dim-quarters. Key blocks of 64.
#define AKB 64
#define AQR 64

__global__ void __launch_bounds__(256) attn_kernel(
    const float* __restrict__ Q, const float* __restrict__ Kg,
    const float* __restrict__ Vg, float* __restrict__ ctx)
{
    __shared__ float Ks[AKB][DK];
    __shared__ float Vs[AKB][DK];
    __shared__ float Ss[AQR][AKB];   // xor-swizzled columns

    const int tid = threadIdx.x;
    const int r   = tid >> 2;        // local query row 0..63
    const int j   = tid & 3;         // dim quarter
    const int bh  = blockIdx.y;      // 0..31
    const int q0  = blockIdx.x * AQR;
    const int swz = r & 31;

    // load q row segment into registers
    float qreg[16];
    {
        const float* qp = Q + ((size_t)bh * SEQ + q0 + r) * DK + j * 16;
        #pragma unroll
        for (int i = 0; i < 4; i++)
            *(float4*)&qreg[i * 4] = *(const float4*)(qp + i * 4);
    }

    float Ov[16];
    #pragma unroll
    for (int i = 0; i < 16; i++) Ov[i] = 0.0f;
    float mrun = -1e30f, lrun = 0.0f;

    const float* Kbh = Kg + (size_t)bh * SEQ * DK;
    const float* Vbh = Vg + (size_t)bh * SEQ * DK;

    for (int kb = 0; kb < SEQ; kb += AKB) {
        // cooperative K/V tile load: 64x64 each
        #pragma unroll
        for (int i = 0; i < 4; i++) {
            const int vdx = tid + i * 256;       // float4 index 0..1023
            const int rr  = vdx >> 4;
            const int cc  = (vdx & 15) << 2;
            *(float4*)&Ks[rr][cc] = *(const float4*)(Kbh + (size_t)(kb + rr) * DK + cc);
            *(float4*)&Vs[rr][cc] = *(const float4*)(Vbh + (size_t)(kb + rr) * DK + cc);
        }
        __syncthreads();

        // scores for this row: each thread does 1/4 of each dot, shfl-reduce
        float rowmax = -1e30f;
        #pragma unroll 4
        for (int kk = 0; kk < AKB; kk++) {
            float s = 0.0f;
            #pragma unroll
            for (int d = 0; d < 16; d += 4) {
                float4 kv = *(const float4*)&Ks[kk][j * 16 + d];
                s = fmaf(qreg[d + 0], kv.x, s);
                s = fmaf(qreg[d + 1], kv.y, s);
                s = fmaf(qreg[d + 2], kv.z, s);
                s = fmaf(qreg[d + 3], kv.w, s);
            }
            s += __shfl_xor_sync(0xffffffffu, s, 1);
            s += __shfl_xor_sync(0xffffffffu, s, 2);
            s *= 0.125f;                          // 1/sqrt(64)
            if ((kk & 3) == j) Ss[r][kk ^ swz] = s;
            rowmax = fmaxf(rowmax, s);
        }
        __syncwarp();

        // online softmax rescale
        const float mnew = fmaxf(mrun, rowmax);
        const float corr = __expf(mrun - mnew);
        lrun *= corr;
        #pragma unroll
        for (int d = 0; d < 16; d++) Ov[d] *= corr;

        // P @ V for this thread's 16 output dims
        #pragma unroll 2
        for (int kk = 0; kk < AKB; kk++) {
            const float p = __expf(Ss[r][kk ^ swz] - mnew);
            lrun += p;
            #pragma unroll
            for (int d = 0; d < 16; d += 4) {
                float4 vv = *(const float4*)&Vs[kk][j * 16 + d];
                Ov[d + 0] = fmaf(p, vv.x, Ov[d + 0]);
                Ov[d + 1] = fmaf(p, vv.y, Ov[d + 1]);
                Ov[d + 2] = fmaf(p, vv.z, Ov[d + 2]);
                Ov[d + 3] = fmaf(p, vv.w, Ov[d + 3]);
            }
        }
        mrun = mnew;
        __syncthreads();
    }

    // write ctx in token-major layout [B,S,1024]
    const int b = bh >> 4, h = bh & 15;
    const float inv = 1.0f / lrun;
    float* op = ctx + ((size_t)(b * SEQ + q0 + r)) * D_MODEL + h * DK + j * 16;
    #pragma unroll
    for (int i = 0; i < 4; i++) {
        float4 o;
        o.x = Ov[i * 4 + 0] * inv;
        o.y = Ov[i * 4 + 1] * inv;
        o.z = Ov[i * 4 + 2] * inv;
        o.w = Ov[i * 4 + 3] * inv;
        *(float4*)(op + i * 4) = o;
    }
}

// ------------------------------ LayerNorm ----------------------------------
__global__ void __launch_bounds__(256) ln_kernel(
    const float* __restrict__ X, const float* __restrict__ G,
    const float* __restrict__ Bb, float* __restrict__ Y)
{
    __shared__ float red[8];
    __shared__ float stat[2];
    const int row = blockIdx.x;
    const int tid = threadIdx.x;
    const int lane = tid & 31, warp = tid >> 5;

    float4 v = *(const float4*)(X + (size_t)row * D_MODEL + tid * 4);

    float s = v.x + v.y + v.z + v.w;
    #pragma unroll
    for (int o = 16; o; o >>= 1) s += __shfl_xor_sync(0xffffffffu, s, o);
    if (lane == 0) red[warp] = s;
    __syncthreads();
    if (tid == 0) {
        float t = 0.0f;
        #pragma unroll
        for (int i = 0; i < 8; i++) t += red[i];
        stat[0] = t * (1.0f / D_MODEL);
    }
    __syncthreads();
    const float mu = stat[0];

    const float d0 = v.x - mu, d1 = v.y - mu, d2 = v.z - mu, d3 = v.w - mu;
    float q = d0 * d0 + d1 * d1 + d2 * d2 + d3 * d3;
    #pragma unroll
    for (int o = 16; o; o >>= 1) q += __shfl_xor_sync(0xffffffffu, q, o);
    if (lane == 0) red[warp] = q;
    __syncthreads();
    if (tid == 0) {
        float t = 0.0f;
        #pragma unroll
        for (int i = 0; i < 8; i++) t += red[i];
        stat[1] = rsqrtf(t * (1.0f / D_MODEL) + EPS);
    }
    __syncthreads();
    const float rstd = stat[1];

    const int c = tid * 4;
    float4 gg = *(const float4*)(G + c);
    float4 bb = *(const float4*)(Bb + c);
    float4 o;
    o.x = d0 * rstd * gg.x + bb.x;
    o.y = d1 * rstd * gg.y + bb.y;
    o.z = d2 * rstd * gg.z + bb.z;
    o.w = d3 * rstd * gg.w + bb.w;
    *(float4*)(Y + (size_t)row * D_MODEL + c) = o;
}

// ------------------------------ launch -------------------------------------
extern "C" void kernel_launch(void* const* d_in, const int* in_sizes, int n_in,
                              void* d_out, int out_size)
{
    const float* x     = (const float*)d_in[0];
    const float* wq    = (const float*)d_in[1];
    const float* bq    = (const float*)d_in[2];
    const float* wk    = (const float*)d_in[3];
    const float* bk    = (const float*)d_in[4];
    const float* wv    = (const float*)d_in[5];
    const float* bv    = (const float*)d_in[6];
    const float* wo    = (const float*)d_in[7];
    const float* bo    = (const float*)d_in[8];
    const float* ln1_g = (const float*)d_in[9];
    const float* ln1_b = (const float*)d_in[10];
    const float* w1    = (const float*)d_in[11];
    const float* b1    = (const float*)d_in[12];
    const float* w2    = (const float*)d_in[13];
    const float* b2    = (const float*)d_in[14];
    const float* ln2_g = (const float*)d_in[15];
    const float* ln2_b = (const float*)d_in[16];
    float* out = (float*)d_out;

    float *q, *k, *v, *ctx, *y, *attn, *h;
    cudaGetSymbolAddress((void**)&q,    g_q);
    cudaGetSymbolAddress((void**)&k,    g_k);
    cudaGetSymbolAddress((void**)&v,    g_v);
    cudaGetSymbolAddress((void**)&ctx,  g_ctx);
    cudaGetSymbolAddress((void**)&y,    g_y);
    cudaGetSymbolAddress((void**)&attn, g_attn);
    cudaGetSymbolAddress((void**)&h,    g_h);

    const dim3 blk(256);
    const dim3 gD(D_MODEL / BN, NTOK / BM);   // (8, 32)
    const dim3 gF(DFF / BN,     NTOK / BM);   // (32, 32)

    // 1) QKV projections (scatter into [B,H,S,Dk])
    sgemm_kernel<MODE_QKV><<<gD, blk>>>(x, wq, bq, nullptr, q, NTOK, D_MODEL, D_MODEL);
    sgemm_kernel<MODE_QKV><<<gD, blk>>>(x, wk, bk, nullptr, k, NTOK, D_MODEL, D_MODEL);
    sgemm_kernel<MODE_QKV><<<gD, blk>>>(x, wv, bv, nullptr, v, NTOK, D_MODEL, D_MODEL);

    // 2) flash attention
    attn_kernel<<<dim3(SEQ / AQR, 2 * NHEAD), blk>>>(q, k, v, ctx);

    // 3) O projection + residual
    sgemm_kernel<MODE_RES><<<gD, blk>>>(ctx, wo, bo, x, y, NTOK, D_MODEL, D_MODEL);

    // 4) LN1
    ln_kernel<<<NTOK, blk>>>(y, ln1_g, ln1_b, attn);

    // 5) FF1 + GELU
    sgemm_kernel<MODE_GELU><<<gF, blk>>>(attn, w1, b1, nullptr, h, NTOK, DFF, D_MODEL);

    // 6) FF2 + residual
    sgemm_kernel<MODE_RES><<<gD, blk>>>(h, w2, b2, attn, y, NTOK, D_MODEL, DFF);

    // 7) LN2 -> output
    ln_kernel<<<NTOK, blk>>>(y, ln2_g, ln2_b, out);
}

// round 3
// speedup vs baseline: 1.2526x; 1.2526x over previous
#include <cuda_runtime.h>
#include <cuda_bf16.h>
#include <math.h>
#include <stdint.h>

// ---------------------------------------------------------------------------
// TransformerBlock B=2,S=2048,D=1024,H=16,Dk=64,DFF=4096
// GEMMs via mma.sync bf16 (3-term hi/lo split => fp32-class accuracy).
// ---------------------------------------------------------------------------

#define D_MODEL 1024
#define NTOK    4096
#define NHEAD   16
#define DK      64
#define DFF     4096
#define SEQ     2048
#define EPS     1e-5f

typedef __nv_bfloat16  bf16;
typedef __nv_bfloat162 bf162;

// ------------------------- scratch (static device mem) ---------------------
__device__ float g_q[NTOK * D_MODEL];
__device__ float g_k[NTOK * D_MODEL];
__device__ float g_v[NTOK * D_MODEL];
__device__ float g_y[NTOK * D_MODEL];
__device__ float g_attn[NTOK * D_MODEL];

__device__ bf16 g_x_h[NTOK * D_MODEL],   g_x_l[NTOK * D_MODEL];
__device__ bf16 g_ctx_h[NTOK * D_MODEL], g_ctx_l[NTOK * D_MODEL];
__device__ bf16 g_at_h[NTOK * D_MODEL],  g_at_l[NTOK * D_MODEL];
__device__ bf16 g_h_h[NTOK * DFF],       g_h_l[NTOK * DFF];
__device__ bf16 g_wq_h[D_MODEL * D_MODEL], g_wq_l[D_MODEL * D_MODEL];
__device__ bf16 g_wk_h[D_MODEL * D_MODEL], g_wk_l[D_MODEL * D_MODEL];
__device__ bf16 g_wv_h[D_MODEL * D_MODEL], g_wv_l[D_MODEL * D_MODEL];
__device__ bf16 g_wo_h[D_MODEL * D_MODEL], g_wo_l[D_MODEL * D_MODEL];
__device__ bf16 g_w1_h[DFF * D_MODEL],     g_w1_l[DFF * D_MODEL];
__device__ bf16 g_w2_h[D_MODEL * DFF],     g_w2_l[D_MODEL * DFF];

// ------------------------------ helpers ------------------------------------
__device__ __forceinline__ uint32_t smem_u32(const void* p) {
    uint32_t a;
    asm("{ .reg .u64 t; cvta.to.shared.u64 t, %1; cvt.u32.u64 %0, t; }" : "=r"(a) : "l"(p));
    return a;
}
#define CP_ASYNC16(dst, src) \
    asm volatile("cp.async.cg.shared.global [%0], [%1], 16;" :: "r"(dst), "l"(src))
#define CP_COMMIT() asm volatile("cp.async.commit_group;")
#define CP_WAIT0()  asm volatile("cp.async.wait_group 0;" ::: "memory")

#define LDMATRIX_X4(r0, r1, r2, r3, a) \
    asm volatile("ldmatrix.sync.aligned.m8n8.x4.shared.b16 {%0,%1,%2,%3}, [%4];" \
                 : "=r"(r0), "=r"(r1), "=r"(r2), "=r"(r3) : "r"(a))

#define MMA16816(c, a, b) \
    asm volatile("mma.sync.aligned.m16n8k16.row.col.f32.bf16.bf16.f32 " \
                 "{%0,%1,%2,%3}, {%4,%5,%6,%7}, {%8,%9}, {%0,%1,%2,%3};" \
                 : "+f"((c)[0]), "+f"((c)[1]), "+f"((c)[2]), "+f"((c)[3]) \
                 : "r"((a)[0]), "r"((a)[1]), "r"((a)[2]), "r"((a)[3]), \
                   "r"((b)[0]), "r"((b)[1]))

__device__ __forceinline__ float gelu_f(float x) {
    return 0.5f * x * (1.0f + erff(x * 0.70710678118654752f));
}
__device__ __forceinline__ void bsplit(float x, bf16& h, bf16& l) {
    h = __float2bfloat16(x);
    l = __float2bfloat16(x - __bfloat162float(h));
}

// ------------------------------ MMA GEMM -----------------------------------
// C[M,N] = (Ah+Al)[M,K] @ (Bh+Bl)[N,K]^T  (3-term bf16, fp32 accum)
#define MODE_QKV    1
#define MODE_RES    2
#define MODE_GELUHL 3

#define ROWB   80            // padded row bytes (32 bf16 = 64B data + 16B pad)
#define TILEB  (128 * ROWB)  // 10240
#define STAGEB (4 * TILEB)   // 40960
#define GEMM_SMEM (2 * STAGEB)

template <int MODE>
__global__ void __launch_bounds__(256, 2) gemm_mma(
    const bf16* __restrict__ Ah, const bf16* __restrict__ Al,
    const bf16* __restrict__ Bh, const bf16* __restrict__ Bl,
    const float* __restrict__ bias, const float* __restrict__ res,
    float* __restrict__ Cf, bf16* __restrict__ Chi, bf16* __restrict__ Clo,
    int M, int N, int K)
{
    extern __shared__ __align__(128) char dsm[];
    const uint32_t sbase = smem_u32(dsm);

    const int tid    = threadIdx.x;
    const int lane   = tid & 31;
    const int warp   = tid >> 5;
    const int warp_m = warp & 3;        // 4 along M -> 32 rows each
    const int warp_n = warp >> 2;       // 2 along N -> 64 cols each
    const int brow   = blockIdx.y * 128;
    const int bcol   = blockIdx.x * 128;

    // ---- cp.async assignment: thread tid>>6 picks tile, handles 2 rows ----
    const int ltile = tid >> 6;         // 0:Ah 1:Al 2:Bh 3:Bl
    const int trow  = (tid & 63) * 2;
    const bf16* gsrc;
    {
        const bf16* t0 = Ah + (size_t)brow * K;
        const bf16* t1 = Al + (size_t)brow * K;
        const bf16* t2 = Bh + (size_t)bcol * K;
        const bf16* t3 = Bl + (size_t)bcol * K;
        gsrc = (ltile == 0) ? t0 : (ltile == 1) ? t1 : (ltile == 2) ? t2 : t3;
    }
    const uint32_t sdst0 = sbase + ltile * TILEB + trow * ROWB;

    // ---- ldmatrix lane addresses (within tile, k0=0) ----
    const int g = lane >> 3, r = lane & 7;
    // A: rows (g&1)*8 + r, col 16B chunk (g>>1)
    const uint32_t aoff = (uint32_t)((warp_m * 32 + (g & 1) * 8 + r) * ROWB + (g >> 1) * 16);
    // B: rows (g>>1)*8 + r, col 16B chunk (g&1)
    const uint32_t boff = (uint32_t)((warp_n * 64 + (g >> 1) * 8 + r) * ROWB + (g & 1) * 16);

    float acc[2][8][4];
    #pragma unroll
    for (int i = 0; i < 2; i++)
        #pragma unroll
        for (int j = 0; j < 8; j++)
            #pragma unroll
            for (int c = 0; c < 4; c++) acc[i][j][c] = 0.0f;

    const int T = K >> 5;   // BK = 32

    // prologue: stage 0
    {
        const bf16* rp = gsrc;
        #pragma unroll
        for (int j = 0; j < 2; j++)
            #pragma unroll
            for (int c = 0; c < 4; c++)
                CP_ASYNC16(sdst0 + j * ROWB + c * 16, rp + (size_t)(trow + j) * K + c * 8);
        CP_COMMIT();
        CP_WAIT0();
        __syncthreads();
    }

    for (int t = 0; t < T; t++) {
        const uint32_t cur = sbase + (uint32_t)(t & 1) * STAGEB;
        if (t + 1 < T) {
            const int k0 = (t + 1) * 32;
            const uint32_t nxt = sdst0 + (uint32_t)((t + 1) & 1) * STAGEB;
            const bf16* rp = gsrc + k0;
            #pragma unroll
            for (int j = 0; j < 2; j++)
                #pragma unroll
                for (int c = 0; c < 4; c++)
                    CP_ASYNC16(nxt + j * ROWB + c * 16, rp + (size_t)(trow + j) * K + c * 8);
            CP_COMMIT();
        }

        const uint32_t sAh = cur + 0 * TILEB + aoff;
        const uint32_t sAl = cur + 1 * TILEB + aoff;
        const uint32_t sBh = cur + 2 * TILEB + boff;
        const uint32_t sBl = cur + 3 * TILEB + boff;

        #pragma unroll
        for (int ks = 0; ks < 2; ks++) {
            const uint32_t ko = ks * 32;   // 16 bf16 = 32B
            uint32_t ah[2][4], al[2][4], bb[8][2];

            #pragma unroll
            for (int mi = 0; mi < 2; mi++) {
                LDMATRIX_X4(ah[mi][0], ah[mi][1], ah[mi][2], ah[mi][3],
                            sAh + mi * (16 * ROWB) + ko);
                LDMATRIX_X4(al[mi][0], al[mi][1], al[mi][2], al[mi][3],
                            sAl + mi * (16 * ROWB) + ko);
            }
            // Bh
            #pragma unroll
            for (int np = 0; np < 4; np++) {
                LDMATRIX_X4(bb[np * 2][0], bb[np * 2][1], bb[np * 2 + 1][0], bb[np * 2 + 1][1],
                            sBh + np * (16 * ROWB) + ko);
            }
            #pragma unroll
            for (int mi = 0; mi < 2; mi++)
                #pragma unroll
                for (int ni = 0; ni < 8; ni++) {
                    MMA16816(acc[mi][ni], ah[mi], bb[ni]);
                }
            #pragma unroll
            for (int mi = 0; mi < 2; mi++)
                #pragma unroll
                for (int ni = 0; ni < 8; ni++) {
                    MMA16816(acc[mi][ni], al[mi], bb[ni]);
                }
            // Bl (overwrite bb)
            #pragma unroll
            for (int np = 0; np < 4; np++) {
                LDMATRIX_X4(bb[np * 2][0], bb[np * 2][1], bb[np * 2 + 1][0], bb[np * 2 + 1][1],
                            sBl + np * (16 * ROWB) + ko);
            }
            #pragma unroll
            for (int mi = 0; mi < 2; mi++)
                #pragma unroll
                for (int ni = 0; ni < 8; ni++) {
                    MMA16816(acc[mi][ni], ah[mi], bb[ni]);
                }
        }

        if (t + 1 < T) CP_WAIT0();
        __syncthreads();
    }

    // ------------------------------ epilogue -------------------------------
    const int mbase = brow + warp_m * 32 + (lane >> 2);
    const int nbase = bcol + warp_n * 64 + (lane & 3) * 2;

    #pragma unroll
    for (int mi = 0; mi < 2; mi++) {
        #pragma unroll
        for (int half = 0; half < 2; half++) {     // c0c1 vs c2c3 (row +8)
            const int m = mbase + mi * 16 + half * 8;
            #pragma unroll
            for (int ni = 0; ni < 8; ni++) {
                const int n = nbase + ni * 8;
                float vx = acc[mi][ni][half * 2 + 0];
                float vy = acc[mi][ni][half * 2 + 1];
                const float2 bb2 = *(const float2*)(bias + n);
                vx += bb2.x; vy += bb2.y;
                if (MODE == MODE_RES) {
                    const float2 rr = *(const float2*)(res + (size_t)m * N + n);
                    vx += rr.x; vy += rr.y;
                    float2 o; o.x = vx; o.y = vy;
                    *(float2*)(Cf + (size_t)m * N + n) = o;
                } else if (MODE == MODE_QKV) {
                    const int bq = m >> 11, sq = m & 2047;
                    const int hq = n >> 6,  dq = n & 63;
                    float2 o; o.x = vx; o.y = vy;
                    *(float2*)(Cf + ((size_t)(bq * NHEAD + hq) * SEQ + sq) * DK + dq) = o;
                } else {  // GELUHL
                    vx = gelu_f(vx); vy = gelu_f(vy);
                    bf162 h2, l2;
                    bsplit(vx, h2.x, l2.x);
                    bsplit(vy, h2.y, l2.y);
                    *(bf162*)(Chi + (size_t)m * N + n) = h2;
                    *(bf162*)(Clo + (size_t)m * N + n) = l2;
                }
            }
        }
    }
}

// ------------------------- fp32 -> bf16 hi/lo split ------------------------
__global__ void __launch_bounds__(256) split_kernel(
    const float4* __restrict__ src, bf162* __restrict__ hi, bf162* __restrict__ lo, int n4)
{
    const int i = blockIdx.x * blockDim.x + threadIdx.x;
    if (i >= n4) return;
    float4 v = src[i];
    bf162 h0, l0, h1, l1;
    bsplit(v.x, h0.x, l0.x); bsplit(v.y, h0.y, l0.y);
    bsplit(v.z, h1.x, l1.x); bsplit(v.w, h1.y, l1.y);
    hi[i * 2 + 0] = h0; lo[i * 2 + 0] = l0;
    hi[i * 2 + 1] = h1; lo[i * 2 + 1] = l1;
}

// -------------------------- flash attention (fp32) -------------------------
#define AKB 64
#define AQR 64

__global__ void __launch_bounds__(256) attn_kernel(
    const float* __restrict__ Q, const float* __restrict__ Kg,
    const float* __restrict__ Vg, bf16* __restrict__ ctx_h, bf16* __restrict__ ctx_l)
{
    __shared__ float Ks[AKB][DK];
    __shared__ float Vs[AKB][DK];
    __shared__ float Ss[AQR][AKB];

    const int tid = threadIdx.x;
    const int r   = tid >> 2;
    const int j   = tid & 3;
    const int bh  = blockIdx.y;
    const int q0  = blockIdx.x * AQR;
    const int swz = r & 31;

    float qreg[16];
    {
        const float* qp = Q + ((size_t)bh * SEQ + q0 + r) * DK + j * 16;
        #pragma unroll
        for (int i = 0; i < 4; i++)
            *(float4*)&qreg[i * 4] = *(const float4*)(qp + i * 4);
    }

    float Ov[16];
    #pragma unroll
    for (int i = 0; i < 16; i++) Ov[i] = 0.0f;
    float mrun = -1e30f, lrun = 0.0f;

    const float* Kbh = Kg + (size_t)bh * SEQ * DK;
    const float* Vbh = Vg + (size_t)bh * SEQ * DK;

    for (int kb = 0; kb < SEQ; kb += AKB) {
        #pragma unroll
        for (int i = 0; i < 4; i++) {
            const int vdx = tid + i * 256;
            const int rr  = vdx >> 4;
            const int cc  = (vdx & 15) << 2;
            *(float4*)&Ks[rr][cc] = *(const float4*)(Kbh + (size_t)(kb + rr) * DK + cc);
            *(float4*)&Vs[rr][cc] = *(const float4*)(Vbh + (size_t)(kb + rr) * DK + cc);
        }
        __syncthreads();

        float rowmax = -1e30f;
        #pragma unroll 4
        for (int kk = 0; kk < AKB; kk++) {
            float s = 0.0f;
            #pragma unroll
            for (int d = 0; d < 16; d += 4) {
                float4 kv = *(const float4*)&Ks[kk][j * 16 + d];
                s = fmaf(qreg[d + 0], kv.x, s);
                s = fmaf(qreg[d + 1], kv.y, s);
                s = fmaf(qreg[d + 2], kv.z, s);
                s = fmaf(qreg[d + 3], kv.w, s);
            }
            s += __shfl_xor_sync(0xffffffffu, s, 1);
            s += __shfl_xor_sync(0xffffffffu, s, 2);
            s *= 0.125f;
            if ((kk & 3) == j) Ss[r][kk ^ swz] = s;
            rowmax = fmaxf(rowmax, s);
        }
        __syncwarp();

        const float mnew = fmaxf(mrun, rowmax);
        const float corr = __expf(mrun - mnew);
        lrun *= corr;
        #pragma unroll
        for (int d = 0; d < 16; d++) Ov[d] *= corr;

        #pragma unroll 2
        for (int kk = 0; kk < AKB; kk++) {
            const float p = __expf(Ss[r][kk ^ swz] - mnew);
            lrun += p;
            #pragma unroll
            for (int d = 0; d < 16; d += 4) {
                float4 vv = *(const float4*)&Vs[kk][j * 16 + d];
                Ov[d + 0] = fmaf(p, vv.x, Ov[d + 0]);
                Ov[d + 1] = fmaf(p, vv.y, Ov[d + 1]);
                Ov[d + 2] = fmaf(p, vv.z, Ov[d + 2]);
                Ov[d + 3] = fmaf(p, vv.w, Ov[d + 3]);
            }
        }
        mrun = mnew;
        __syncthreads();
    }

    const int b = bh >> 4, h = bh & 15;
    const float inv = 1.0f / lrun;
    const size_t off = ((size_t)(b * SEQ + q0 + r)) * D_MODEL + h * DK + j * 16;
    #pragma unroll
    for (int i = 0; i < 16; i += 2) {
        const float a = Ov[i] * inv, c = Ov[i + 1] * inv;
        bf162 hp, lp;
        bsplit(a, hp.x, lp.x);
        bsplit(c, hp.y, lp.y);
        *(bf162*)(ctx_h + off + i) = hp;
        *(bf162*)(ctx_l + off + i) = lp;
    }
}

// ------------------------------ LayerNorm ----------------------------------
template <bool HL>
__global__ void __launch_bounds__(256) ln_kernel(
    const float* __restrict__ X, const float* __restrict__ G,
    const float* __restrict__ Bb, float* __restrict__ Y,
    bf16* __restrict__ Yh, bf16* __restrict__ Yl)
{
    __shared__ float red[8];
    __shared__ float stat[2];
    const int row = blockIdx.x;
    const int tid = threadIdx.x;
    const int lane = tid & 31, warp = tid >> 5;

    float4 v = *(const float4*)(X + (size_t)row * D_MODEL + tid * 4);

    float s = v.x + v.y + v.z + v.w;
    #pragma unroll
    for (int o = 16; o; o >>= 1) s += __shfl_xor_sync(0xffffffffu, s, o);
    if (lane == 0) red[warp] = s;
    __syncthreads();
    if (tid == 0) {
        float t = 0.0f;
        #pragma unroll
        for (int i = 0; i < 8; i++) t += red[i];
        stat[0] = t * (1.0f / D_MODEL);
    }
    __syncthreads();
    const float mu = stat[0];

    const float d0 = v.x - mu, d1 = v.y - mu, d2 = v.z - mu, d3 = v.w - mu;
    float q = d0 * d0 + d1 * d1 + d2 * d2 + d3 * d3;
    #pragma unroll
    for (int o = 16; o; o >>= 1) q += __shfl_xor_sync(0xffffffffu, q, o);
    if (lane == 0) red[warp] = q;
    __syncthreads();
    if (tid == 0) {
        float t = 0.0f;
        #pragma unroll
        for (int i = 0; i < 8; i++) t += red[i];
        stat[1] = rsqrtf(t * (1.0f / D_MODEL) + EPS);
    }
    __syncthreads();
    const float rstd = stat[1];

    const int c = tid * 4;
    float4 gg = *(const float4*)(G + c);
    float4 bb = *(const float4*)(Bb + c);
    float4 o;
    o.x = d0 * rstd * gg.x + bb.x;
    o.y = d1 * rstd * gg.y + bb.y;
    o.z = d2 * rstd * gg.z + bb.z;
    o.w = d3 * rstd * gg.w + bb.w;
    *(float4*)(Y + (size_t)row * D_MODEL + c) = o;

    if (HL) {
        bf162 h0, l0, h1, l1;
        bsplit(o.x, h0.x, l0.x); bsplit(o.y, h0.y, l0.y);
        bsplit(o.z, h1.x, l1.x); bsplit(o.w, h1.y, l1.y);
        *(bf162*)(Yh + (size_t)row * D_MODEL + c)     = h0;
        *(bf162*)(Yl + (size_t)row * D_MODEL + c)     = l0;
        *(bf162*)(Yh + (size_t)row * D_MODEL + c + 2) = h1;
        *(bf162*)(Yl + (size_t)row * D_MODEL + c + 2) = l1;
    }
}

// ------------------------------ launch -------------------------------------
static inline void split_launch(const float* src, bf16* hi, bf16* lo, int n) {
    const int n4 = n / 4;
    split_kernel<<<(n4 + 255) / 256, 256>>>((const float4*)src, (bf162*)hi, (bf162*)lo, n4);
}

extern "C" void kernel_launch(void* const* d_in, const int* in_sizes, int n_in,
                              void* d_out, int out_size)
{
    const float* x     = (const float*)d_in[0];
    const float* wq    = (const float*)d_in[1];
    const float* bq    = (const float*)d_in[2];
    const float* wk    = (const float*)d_in[3];
    const float* bk    = (const float*)d_in[4];
    const float* wv    = (const float*)d_in[5];
    const float* bv    = (const float*)d_in[6];
    const float* wo    = (const float*)d_in[7];
    const float* bo    = (const float*)d_in[8];
    const float* ln1_g = (const float*)d_in[9];
    const float* ln1_b = (const float*)d_in[10];
    const float* w1    = (const float*)d_in[11];
    const float* b1    = (const float*)d_in[12];
    const float* w2    = (const float*)d_in[13];
    const float* b2    = (const float*)d_in[14];
    const float* ln2_g = (const float*)d_in[15];
    const float* ln2_b = (const float*)d_in[16];
    float* out = (float*)d_out;

    float *q, *k, *v, *y, *attn;
    bf16 *xh, *xl, *ch, *cl, *ah, *al, *hh, *hl;
    bf16 *wqh, *wql, *wkh, *wkl, *wvh, *wvl, *woh, *wol, *w1h, *w1l, *w2h, *w2l;
    cudaGetSymbolAddress((void**)&q, g_q);
    cudaGetSymbolAddress((void**)&k, g_k);
    cudaGetSymbolAddress((void**)&v, g_v);
    cudaGetSymbolAddress((void**)&y, g_y);
    cudaGetSymbolAddress((void**)&attn, g_attn);
    cudaGetSymbolAddress((void**)&xh, g_x_h);   cudaGetSymbolAddress((void**)&xl, g_x_l);
    cudaGetSymbolAddress((void**)&ch, g_ctx_h); cudaGetSymbolAddress((void**)&cl, g_ctx_l);
    cudaGetSymbolAddress((void**)&ah, g_at_h);  cudaGetSymbolAddress((void**)&al, g_at_l);
    cudaGetSymbolAddress((void**)&hh, g_h_h);   cudaGetSymbolAddress((void**)&hl, g_h_l);
    cudaGetSymbolAddress((void**)&wqh, g_wq_h); cudaGetSymbolAddress((void**)&wql, g_wq_l);
    cudaGetSymbolAddress((void**)&wkh, g_wk_h); cudaGetSymbolAddress((void**)&wkl, g_wk_l);
    cudaGetSymbolAddress((void**)&wvh, g_wv_h); cudaGetSymbolAddress((void**)&wvl, g_wv_l);
    cudaGetSymbolAddress((void**)&woh, g_wo_h); cudaGetSymbolAddress((void**)&wol, g_wo_l);
    cudaGetSymbolAddress((void**)&w1h, g_w1_h); cudaGetSymbolAddress((void**)&w1l, g_w1_l);
    cudaGetSymbolAddress((void**)&w2h, g_w2_h); cudaGetSymbolAddress((void**)&w2l, g_w2_l);

    cudaFuncSetAttribute(gemm_mma<MODE_QKV>,    cudaFuncAttributeMaxDynamicSharedMemorySize, GEMM_SMEM);
    cudaFuncSetAttribute(gemm_mma<MODE_RES>,    cudaFuncAttributeMaxDynamicSharedMemorySize, GEMM_SMEM);
    cudaFuncSetAttribute(gemm_mma<MODE_GELUHL>, cudaFuncAttributeMaxDynamicSharedMemorySize, GEMM_SMEM);

    // ---- splits (weights + x) ----
    split_launch(x,  xh,  xl,  NTOK * D_MODEL);
    split_launch(wq, wqh, wql, D_MODEL * D_MODEL);
    split_launch(wk, wkh, wkl, D_MODEL * D_MODEL);
    split_launch(wv, wvh, wvl, D_MODEL * D_MODEL);
    split_launch(wo, woh, wol, D_MODEL * D_MODEL);
    split_launch(w1, w1h, w1l, DFF * D_MODEL);
    split_launch(w2, w2h, w2l, D_MODEL * DFF);

    const dim3 blk(256);
    const dim3 gD(D_MODEL / 128, NTOK / 128);   // (8, 32)
    const dim3 gF(DFF / 128,     NTOK / 128);   // (32, 32)

    // 1) QKV projections -> fp32 [B,H,S,Dk]
    gemm_mma<MODE_QKV><<<gD, blk, GEMM_SMEM>>>(xh, xl, wqh, wql, bq, nullptr, q, nullptr, nullptr,
                                               NTOK, D_MODEL, D_MODEL);
    gemm_mma<MODE_QKV><<<gD, blk, GEMM_SMEM>>>(xh, xl, wkh, wkl, bk, nullptr, k, nullptr, nullptr,
                                               NTOK, D_MODEL, D_MODEL);
    gemm_mma<MODE_QKV><<<gD, blk, GEMM_SMEM>>>(xh, xl, wvh, wvl, bv, nullptr, v, nullptr, nullptr,
                                               NTOK, D_MODEL, D_MODEL);

    // 2) flash attention -> ctx hi/lo
    attn_kernel<<<dim3(SEQ / AQR, 2 * NHEAD), blk>>>(q, k, v, ch, cl);

    // 3) O projection + residual -> y
    gemm_mma<MODE_RES><<<gD, blk, GEMM_SMEM>>>(ch, cl, woh, wol, bo, x, y, nullptr, nullptr,
                                               NTOK, D_MODEL, D_MODEL);

    // 4) LN1 -> attn fp32 + hi/lo
    ln_kernel<true><<<NTOK, blk>>>(y, ln1_g, ln1_b, attn, ah, al);

    // 5) FF1 + GELU -> h hi/lo
    gemm_mma<MODE_GELUHL><<<gF, blk, GEMM_SMEM>>>(ah, al, w1h, w1l, b1, nullptr, nullptr, hh, hl,
                                                  NTOK, DFF, D_MODEL);

    // 6) FF2 + residual -> y
    gemm_mma<MODE_RES><<<gD, blk, GEMM_SMEM>>>(hh, hl, w2h, w2l, b2, attn, y, nullptr, nullptr,
                                               NTOK, D_MODEL, DFF);

    // 7) LN2 -> out
    ln_kernel<false><<<NTOK, blk>>>(y, ln2_g, ln2_b, out, nullptr, nullptr);
}

// round 5
// speedup vs baseline: 7.1774x; 5.7298x over previous
#include <cuda_runtime.h>
#include <cuda_fp16.h>
#include <math.h>
#include <stdint.h>

// ---------------------------------------------------------------------------
// TransformerBlock B=2,S=2048,D=1024,H=16,Dk=64,DFF=4096
// GEMMs: mma.sync f16, 2-term weight split (A_f16 * (Wh+Wl)).
// Attention: tensor-core flash attention, f16 Q/K/V.
// ---------------------------------------------------------------------------

#define D_MODEL 1024
#define NTOK    4096
#define NHEAD   16
#define DK      64
#define DFF     4096
#define SEQ     2048
#define EPS     1e-5f

// ------------------------- scratch (static device mem) ---------------------
__device__ half  g_q[NTOK * D_MODEL];
__device__ half  g_k[NTOK * D_MODEL];
__device__ half  g_v[NTOK * D_MODEL];
__device__ half  g_ctx[NTOK * D_MODEL];
__device__ half  g_xh[NTOK * D_MODEL];
__device__ half  g_ath[NTOK * D_MODEL];
__device__ half  g_hh[NTOK * DFF];
__device__ float g_y[NTOK * D_MODEL];
__device__ float g_attn[NTOK * D_MODEL];

__device__ half g_wq_h[D_MODEL * D_MODEL], g_wq_l[D_MODEL * D_MODEL];
__device__ half g_wk_h[D_MODEL * D_MODEL], g_wk_l[D_MODEL * D_MODEL];
__device__ half g_wv_h[D_MODEL * D_MODEL], g_wv_l[D_MODEL * D_MODEL];
__device__ half g_wo_h[D_MODEL * D_MODEL], g_wo_l[D_MODEL * D_MODEL];
__device__ half g_w1_h[DFF * D_MODEL],     g_w1_l[DFF * D_MODEL];
__device__ half g_w2_h[D_MODEL * DFF],     g_w2_l[D_MODEL * DFF];

// ------------------------------ helpers ------------------------------------
__device__ __forceinline__ uint32_t smem_u32(const void* p) {
    uint32_t a;
    asm("{ .reg .u64 t; cvta.to.shared.u64 t, %1; cvt.u32.u64 %0, t; }" : "=r"(a) : "l"(p));
    return a;
}
#define CP_ASYNC16(dst, src) \
    asm volatile("cp.async.cg.shared.global [%0], [%1], 16;" :: "r"(dst), "l"(src))
#define CP_COMMIT() asm volatile("cp.async.commit_group;")
#define CP_WAIT0()  asm volatile("cp.async.wait_group 0;" ::: "memory")

#define LDMATRIX_X4(r0, r1, r2, r3, a) \
    asm volatile("ldmatrix.sync.aligned.m8n8.x4.shared.b16 {%0,%1,%2,%3}, [%4];" \
                 : "=r"(r0), "=r"(r1), "=r"(r2), "=r"(r3) : "r"(a))
#define LDMATRIX_X4_TRANS(r0, r1, r2, r3, a) \
    asm volatile("ldmatrix.sync.aligned.m8n8.x4.trans.shared.b16 {%0,%1,%2,%3}, [%4];" \
                 : "=r"(r0), "=r"(r1), "=r"(r2), "=r"(r3) : "r"(a))

#define MMA16816(c, a, b) \
    asm volatile("mma.sync.aligned.m16n8k16.row.col.f32.f16.f16.f32 " \
                 "{%0,%1,%2,%3}, {%4,%5,%6,%7}, {%8,%9}, {%0,%1,%2,%3};" \
                 : "+f"((c)[0]), "+f"((c)[1]), "+f"((c)[2]), "+f"((c)[3]) \
                 : "r"((a)[0]), "r"((a)[1]), "r"((a)[2]), "r"((a)[3]), \
                   "r"((b)[0]), "r"((b)[1]))

__device__ __forceinline__ float gelu_f(float x) {
    return 0.5f * x * (1.0f + erff(x * 0.70710678118654752f));
}
__device__ __forceinline__ void hsplit(float x, half& h, half& l) {
    h = __float2half_rn(x);
    l = __float2half_rn(x - __half2float(h));
}
__device__ __forceinline__ uint32_t h2pack(float a, float b) {
    half2 h = __floats2half2_rn(a, b);
    return *(uint32_t*)&h;
}

// ------------------------------ MMA GEMM -----------------------------------
// C[M,N] = A_f16[M,K] @ (Wh+Wl)[N,K]^T  (2-term weight split, fp32 accum)
#define MODE_QKV  1
#define MODE_RES  2
#define MODE_GELU 3

#define ROWB   80            // padded row bytes (32 f16 = 64B data + 16B pad)
#define TILEB  (128 * ROWB)  // 10240
#define STAGEB (3 * TILEB)   // 30720
#define GEMM_SMEM (2 * STAGEB)

template <int MODE>
__global__ void __launch_bounds__(256, 2) gemm_mma(
    const half* __restrict__ A,
    const half* __restrict__ Bh, const half* __restrict__ Bl,
    const float* __restrict__ bias, const float* __restrict__ res,
    float* __restrict__ Cf, half* __restrict__ Ch,
    int M, int N, int K, float oscale)
{
    extern __shared__ __align__(128) char dsm[];
    const uint32_t sbase = smem_u32(dsm);

    const int tid    = threadIdx.x;
    const int lane   = tid & 31;
    const int warp   = tid >> 5;
    const int warp_m = warp & 3;        // 4 along M -> 32 rows each
    const int warp_n = warp >> 2;       // 2 along N -> 64 cols each
    const int brow   = blockIdx.y * 128;
    const int bcol   = blockIdx.x * 128;

    // cp.async map: each thread: per tile, row tid>>1, chunks (tid&1)*2 + {0,1}
    const int lrow  = tid >> 1;
    const int lcb   = (tid & 1) * 2;
    const half* srcA  = A  + (size_t)(brow + lrow) * K + lcb * 8;
    const half* srcBh = Bh + (size_t)(bcol + lrow) * K + lcb * 8;
    const half* srcBl = Bl + (size_t)(bcol + lrow) * K + lcb * 8;
    const uint32_t dstbase = sbase + (uint32_t)(lrow * ROWB + lcb * 16);

    // ldmatrix lane addresses
    const int g = lane >> 3, r = lane & 7;
    const uint32_t aoff = (uint32_t)((warp_m * 32 + (g & 1) * 8 + r) * ROWB + (g >> 1) * 16);
    const uint32_t boff = (uint32_t)((warp_n * 64 + (g >> 1) * 8 + r) * ROWB + (g & 1) * 16);

    float acc[2][8][4];
    #pragma unroll
    for (int i = 0; i < 2; i++)
        #pragma unroll
        for (int j = 0; j < 8; j++)
            #pragma unroll
            for (int c = 0; c < 4; c++) acc[i][j][c] = 0.0f;

    const int T = K >> 5;   // BK = 32

    // prologue: stage 0
    {
        #pragma unroll
        for (int cc = 0; cc < 2; cc++) {
            CP_ASYNC16(dstbase + 0 * TILEB + cc * 16, srcA  + cc * 8);
            CP_ASYNC16(dstbase + 1 * TILEB + cc * 16, srcBh + cc * 8);
            CP_ASYNC16(dstbase + 2 * TILEB + cc * 16, srcBl + cc * 8);
        }
        CP_COMMIT();
        CP_WAIT0();
        __syncthreads();
    }

    for (int t = 0; t < T; t++) {
        const uint32_t cur = sbase + (uint32_t)(t & 1) * STAGEB;
        if (t + 1 < T) {
            const int k0 = (t + 1) * 32;
            const uint32_t nxt = dstbase + (uint32_t)((t + 1) & 1) * STAGEB;
            #pragma unroll
            for (int cc = 0; cc < 2; cc++) {
                CP_ASYNC16(nxt + 0 * TILEB + cc * 16, srcA  + k0 + cc * 8);
                CP_ASYNC16(nxt + 1 * TILEB + cc * 16, srcBh + k0 + cc * 8);
                CP_ASYNC16(nxt + 2 * TILEB + cc * 16, srcBl + k0 + cc * 8);
            }
            CP_COMMIT();
        }

        const uint32_t sA  = cur + 0 * TILEB + aoff;
        const uint32_t sBh = cur + 1 * TILEB + boff;
        const uint32_t sBl = cur + 2 * TILEB + boff;

        #pragma unroll
        for (int ks = 0; ks < 2; ks++) {
            const uint32_t ko = ks * 32;   // 16 f16 = 32B
            uint32_t a[2][4], bb[8][2];

            #pragma unroll
            for (int mi = 0; mi < 2; mi++)
                LDMATRIX_X4(a[mi][0], a[mi][1], a[mi][2], a[mi][3],
                            sA + mi * (16 * ROWB) + ko);
            // Wh
            #pragma unroll
            for (int np = 0; np < 4; np++)
                LDMATRIX_X4(bb[np * 2][0], bb[np * 2][1], bb[np * 2 + 1][0], bb[np * 2 + 1][1],
                            sBh + np * (16 * ROWB) + ko);
            #pragma unroll
            for (int mi = 0; mi < 2; mi++)
                #pragma unroll
                for (int ni = 0; ni < 8; ni++)
                    MMA16816(acc[mi][ni], a[mi], bb[ni]);
            // Wl
            #pragma unroll
            for (int np = 0; np < 4; np++)
                LDMATRIX_X4(bb[np * 2][0], bb[np * 2][1], bb[np * 2 + 1][0], bb[np * 2 + 1][1],
                            sBl + np * (16 * ROWB) + ko);
            #pragma unroll
            for (int mi = 0; mi < 2; mi++)
                #pragma unroll
                for (int ni = 0; ni < 8; ni++)
                    MMA16816(acc[mi][ni], a[mi], bb[ni]);
        }

        if (t + 1 < T) CP_WAIT0();
        __syncthreads();
    }

    // ------------------------------ epilogue -------------------------------
    const int mbase = brow + warp_m * 32 + (lane >> 2);
    const int nbase = bcol + warp_n * 64 + (lane & 3) * 2;

    #pragma unroll
    for (int mi = 0; mi < 2; mi++) {
        #pragma unroll
        for (int half_ = 0; half_ < 2; half_++) {
            const int m = mbase + mi * 16 + half_ * 8;
            #pragma unroll
            for (int ni = 0; ni < 8; ni++) {
                const int n = nbase + ni * 8;
                float vx = acc[mi][ni][half_ * 2 + 0];
                float vy = acc[mi][ni][half_ * 2 + 1];
                const float2 bb2 = *(const float2*)(bias + n);
                vx += bb2.x; vy += bb2.y;
                if (MODE == MODE_RES) {
                    const float2 rr = *(const float2*)(res + (size_t)m * N + n);
                    float2 o; o.x = vx + rr.x; o.y = vy + rr.y;
                    *(float2*)(Cf + (size_t)m * N + n) = o;
                } else if (MODE == MODE_QKV) {
                    const int bq = m >> 11, sq = m & 2047;
                    const int hq = n >> 6,  dq = n & 63;
                    half2 o = __floats2half2_rn(vx * oscale, vy * oscale);
                    *(half2*)(Ch + ((size_t)(bq * NHEAD + hq) * SEQ + sq) * DK + dq) = o;
                } else {  // GELU
                    half2 o = __floats2half2_rn(gelu_f(vx), gelu_f(vy));
                    *(half2*)(Ch + (size_t)m * N + n) = o;
                }
            }
        }
    }
}

// -------------------- weight split / activation convert --------------------
__global__ void __launch_bounds__(256) split_kernel(
    const float4* __restrict__ src, half2* __restrict__ hi, half2* __restrict__ lo, int n4)
{
    const int i = blockIdx.x * blockDim.x + threadIdx.x;
    if (i >= n4) return;
    float4 v = src[i];
    half2 h0, l0, h1, l1;
    hsplit(v.x, h0.x, l0.x); hsplit(v.y, h0.y, l0.y);
    hsplit(v.z, h1.x, l1.x); hsplit(v.w, h1.y, l1.y);
    hi[i * 2 + 0] = h0; lo[i * 2 + 0] = l0;
    hi[i * 2 + 1] = h1; lo[i * 2 + 1] = l1;
}

__global__ void __launch_bounds__(256) cvt_kernel(
    const float4* __restrict__ src, half2* __restrict__ dst, int n4)
{
    const int i = blockIdx.x * blockDim.x + threadIdx.x;
    if (i >= n4) return;
    float4 v = src[i];
    dst[i * 2 + 0] = __floats2half2_rn(v.x, v.y);
    dst[i * 2 + 1] = __floats2half2_rn(v.z, v.w);
}

// ---------------------- tensor-core flash attention ------------------------
// Q pre-scaled by 1/8. Q/K/V: [B*H, S, 64] f16. ctx: [B, S, 1024] f16.
// CTA: 256 thr = 8 warps x 16 q-rows. Key blocks of 64, double-buffered.
#define KROWB 144
#define ATT_SQ_B  (128 * KROWB)              // 18432
#define ATT_KV_B  (64 * KROWB)               // 9216
#define ATT_SMEM  (ATT_SQ_B + 4 * ATT_KV_B)  // 55296

__global__ void __launch_bounds__(256, 2) attn_tc(
    const half* __restrict__ Qg, const half* __restrict__ Kg,
    const half* __restrict__ Vg, half* __restrict__ ctx)
{
    extern __shared__ __align__(128) char sm[];
    const uint32_t sb = smem_u32(sm);
    const uint32_t sQ = sb;
    const uint32_t sKs[2] = { sb + ATT_SQ_B,                sb + ATT_SQ_B + 2 * ATT_KV_B };
    const uint32_t sVs[2] = { sb + ATT_SQ_B + ATT_KV_B,     sb + ATT_SQ_B + 3 * ATT_KV_B };

    const int tid  = threadIdx.x;
    const int lane = tid & 31;
    const int warp = tid >> 5;
    const int bh   = blockIdx.y;
    const int q0   = blockIdx.x * 128;

    const half* Qp = Qg + ((size_t)bh * SEQ + q0) * DK;
    const half* Kp = Kg + (size_t)bh * SEQ * DK;
    const half* Vp = Vg + (size_t)bh * SEQ * DK;

    // load Q tile (128x64) + K/V block 0 (64x64 each)
    #pragma unroll
    for (int i = 0; i < 4; i++) {
        const int idx = tid + i * 256;
        const int row = idx >> 3, c = idx & 7;
        CP_ASYNC16(sQ + (uint32_t)(row * KROWB + c * 16), Qp + (size_t)row * DK + c * 8);
    }
    #pragma unroll
    for (int i = 0; i < 2; i++) {
        const int idx = tid + i * 256;
        const int row = idx >> 3, c = idx & 7;
        CP_ASYNC16(sKs[0] + (uint32_t)(row * KROWB + c * 16), Kp + (size_t)row * DK + c * 8);
        CP_ASYNC16(sVs[0] + (uint32_t)(row * KROWB + c * 16), Vp + (size_t)row * DK + c * 8);
    }
    CP_COMMIT(); CP_WAIT0();
    __syncthreads();

    const int g = lane >> 3, r8 = lane & 7;

    // Q fragments: warp covers rows [warp*16, warp*16+16)
    uint32_t qa[4][4];
    {
        const uint32_t ao = sQ + (uint32_t)((warp * 16 + (g & 1) * 8 + r8) * KROWB + (g >> 1) * 16);
        #pragma unroll
        for (int kf = 0; kf < 4; kf++)
            LDMATRIX_X4(qa[kf][0], qa[kf][1], qa[kf][2], qa[kf][3], ao + kf * 32);
    }

    float oacc[8][4];
    #pragma unroll
    for (int i = 0; i < 8; i++)
        #pragma unroll
        for (int c = 0; c < 4; c++) oacc[i][c] = 0.0f;
    float mrun0 = -1e30f, mrun1 = -1e30f, lrun0 = 0.0f, lrun1 = 0.0f;

    const uint32_t koff = (uint32_t)(((g >> 1) * 8 + r8) * KROWB + (g & 1) * 16);
    const uint32_t voff = (uint32_t)(((g & 1) * 8 + r8) * KROWB + (g >> 1) * 16);

    for (int kb = 0; kb < SEQ / 64; kb++) {
        if (kb + 1 < SEQ / 64) {
            const uint32_t st = (uint32_t)((kb + 1) & 1);
            const size_t kbase = (size_t)(kb + 1) * 64 * DK;
            #pragma unroll
            for (int i = 0; i < 2; i++) {
                const int idx = tid + i * 256;
                const int row = idx >> 3, c = idx & 7;
                CP_ASYNC16(sKs[st] + (uint32_t)(row * KROWB + c * 16), Kp + kbase + (size_t)row * DK + c * 8);
                CP_ASYNC16(sVs[st] + (uint32_t)(row * KROWB + c * 16), Vp + kbase + (size_t)row * DK + c * 8);
            }
            CP_COMMIT();
        }

        const uint32_t sk = sKs[kb & 1], sv = sVs[kb & 1];

        // ---- S = Q @ K^T ----
        float sf[8][4];
        #pragma unroll
        for (int i = 0; i < 8; i++)
            #pragma unroll
            for (int c = 0; c < 4; c++) sf[i][c] = 0.0f;

        #pragma unroll
        for (int kf = 0; kf < 4; kf++) {
            uint32_t kbv[8][2];
            const uint32_t bo = sk + koff + kf * 32;
            #pragma unroll
            for (int np = 0; np < 4; np++)
                LDMATRIX_X4(kbv[np * 2][0], kbv[np * 2][1], kbv[np * 2 + 1][0], kbv[np * 2 + 1][1],
                            bo + np * (16 * KROWB));
            #pragma unroll
            for (int ni = 0; ni < 8; ni++)
                MMA16816(sf[ni], qa[kf], kbv[ni]);
        }

        // ---- online softmax (rows: lane>>2 and +8) ----
        float mx0 = -1e30f, mx1 = -1e30f;
        #pragma unroll
        for (int ni = 0; ni < 8; ni++) {
            mx0 = fmaxf(mx0, fmaxf(sf[ni][0], sf[ni][1]));
            mx1 = fmaxf(mx1, fmaxf(sf[ni][2], sf[ni][3]));
        }
        mx0 = fmaxf(mx0, __shfl_xor_sync(0xffffffffu, mx0, 1));
        mx0 = fmaxf(mx0, __shfl_xor_sync(0xffffffffu, mx0, 2));
        mx1 = fmaxf(mx1, __shfl_xor_sync(0xffffffffu, mx1, 1));
        mx1 = fmaxf(mx1, __shfl_xor_sync(0xffffffffu, mx1, 2));

        const float mn0 = fmaxf(mrun0, mx0), mn1 = fmaxf(mrun1, mx1);
        const float cr0 = __expf(mrun0 - mn0), cr1 = __expf(mrun1 - mn1);
        float s0 = 0.0f, s1 = 0.0f;
        #pragma unroll
        for (int ni = 0; ni < 8; ni++) {
            sf[ni][0] = __expf(sf[ni][0] - mn0); s0 += sf[ni][0];
            sf[ni][1] = __expf(sf[ni][1] - mn0); s0 += sf[ni][1];
            sf[ni][2] = __expf(sf[ni][2] - mn1); s1 += sf[ni][2];
            sf[ni][3] = __expf(sf[ni][3] - mn1); s1 += sf[ni][3];
        }
        s0 += __shfl_xor_sync(0xffffffffu, s0, 1);
        s0 += __shfl_xor_sync(0xffffffffu, s0, 2);
        s1 += __shfl_xor_sync(0xffffffffu, s1, 1);
        s1 += __shfl_xor_sync(0xffffffffu, s1, 2);
        lrun0 = lrun0 * cr0 + s0;
        lrun1 = lrun1 * cr1 + s1;
        #pragma unroll
        for (int ni = 0; ni < 8; ni++) {
            oacc[ni][0] *= cr0; oacc[ni][1] *= cr0;
            oacc[ni][2] *= cr1; oacc[ni][3] *= cr1;
        }
        mrun0 = mn0; mrun1 = mn1;

        // ---- O += P @ V ----
        #pragma unroll
        for (int kf = 0; kf < 4; kf++) {
            uint32_t pa[4];
            pa[0] = h2pack(sf[2 * kf][0],     sf[2 * kf][1]);
            pa[1] = h2pack(sf[2 * kf][2],     sf[2 * kf][3]);
            pa[2] = h2pack(sf[2 * kf + 1][0], sf[2 * kf + 1][1]);
            pa[3] = h2pack(sf[2 * kf + 1][2], sf[2 * kf + 1][3]);

            uint32_t vb[8][2];
            const uint32_t vo = sv + voff + kf * (16 * KROWB);
            #pragma unroll
            for (int np = 0; np < 4; np++)
                LDMATRIX_X4_TRANS(vb[np * 2][0], vb[np * 2][1], vb[np * 2 + 1][0], vb[np * 2 + 1][1],
                                  vo + np * 32);
            #pragma unroll
            for (int ni = 0; ni < 8; ni++)
                MMA16816(oacc[ni], pa, vb[ni]);
        }

        if (kb + 1 < SEQ / 64) CP_WAIT0();
        __syncthreads();
    }

    // ---- write ctx ----
    const int b = bh >> 4, h = bh & 15;
    const float i0 = 1.0f / lrun0, i1 = 1.0f / lrun1;
    const int tok = q0 + warp * 16 + (lane >> 2);
    half* p0 = ctx + (size_t)(b * SEQ + tok) * D_MODEL + h * DK + (lane & 3) * 2;
    half* p1 = p0 + 8 * D_MODEL;
    #pragma unroll
    for (int ni = 0; ni < 8; ni++) {
        *(half2*)(p0 + ni * 8) = __floats2half2_rn(oacc[ni][0] * i0, oacc[ni][1] * i0);
        *(half2*)(p1 + ni * 8) = __floats2half2_rn(oacc[ni][2] * i1, oacc[ni][3] * i1);
    }
}

// ------------------------------ LayerNorm ----------------------------------
template <bool HOUT>
__global__ void __launch_bounds__(256) ln_kernel(
    const float* __restrict__ X, const float* __restrict__ G,
    const float* __restrict__ Bb, float* __restrict__ Y, half* __restrict__ Yh)
{
    __shared__ float red[8];
    __shared__ float stat[2];
    const int row = blockIdx.x;
    const int tid = threadIdx.x;
    const int lane = tid & 31, warp = tid >> 5;

    float4 v = *(const float4*)(X + (size_t)row * D_MODEL + tid * 4);

    float s = v.x + v.y + v.z + v.w;
    #pragma unroll
    for (int o = 16; o; o >>= 1) s += __shfl_xor_sync(0xffffffffu, s, o);
    if (lane == 0) red[warp] = s;
    __syncthreads();
    if (tid == 0) {
        float t = 0.0f;
        #pragma unroll
        for (int i = 0; i < 8; i++) t += red[i];
        stat[0] = t * (1.0f / D_MODEL);
    }
    __syncthreads();
    const float mu = stat[0];

    const float d0 = v.x - mu, d1 = v.y - mu, d2 = v.z - mu, d3 = v.w - mu;
    float q = d0 * d0 + d1 * d1 + d2 * d2 + d3 * d3;
    #pragma unroll
    for (int o = 16; o; o >>= 1) q += __shfl_xor_sync(0xffffffffu, q, o);
    if (lane == 0) red[warp] = q;
    __syncthreads();
    if (tid == 0) {
        float t = 0.0f;
        #pragma unroll
        for (int i = 0; i < 8; i++) t += red[i];
        stat[1] = rsqrtf(t * (1.0f / D_MODEL) + EPS);
    }
    __syncthreads();
    const float rstd = stat[1];

    const int c = tid * 4;
    float4 gg = *(const float4*)(G + c);
    float4 bb = *(const float4*)(Bb + c);
    float4 o;
    o.x = d0 * rstd * gg.x + bb.x;
    o.y = d1 * rstd * gg.y + bb.y;
    o.z = d2 * rstd * gg.z + bb.z;
    o.w = d3 * rstd * gg.w + bb.w;
    *(float4*)(Y + (size_t)row * D_MODEL + c) = o;

    if (HOUT) {
        *(half2*)(Yh + (size_t)row * D_MODEL + c)     = __floats2half2_rn(o.x, o.y);
        *(half2*)(Yh + (size_t)row * D_MODEL + c + 2) = __floats2half2_rn(o.z, o.w);
    }
}

// ------------------------------ launch -------------------------------------
static inline void split_launch(const float* src, half* hi, half* lo, int n) {
    const int n4 = n / 4;
    split_kernel<<<(n4 + 255) / 256, 256>>>((const float4*)src, (half2*)hi, (half2*)lo, n4);
}

extern "C" void kernel_launch(void* const* d_in, const int* in_sizes, int n_in,
                              void* d_out, int out_size)
{
    const float* x     = (const float*)d_in[0];
    const float* wq    = (const float*)d_in[1];
    const float* bq    = (const float*)d_in[2];
    const float* wk    = (const float*)d_in[3];
    const float* bk    = (const float*)d_in[4];
    const float* wv    = (const float*)d_in[5];
    const float* bv    = (const float*)d_in[6];
    const float* wo    = (const float*)d_in[7];
    const float* bo    = (const float*)d_in[8];
    const float* ln1_g = (const float*)d_in[9];
    const float* ln1_b = (const float*)d_in[10];
    const float* w1    = (const float*)d_in[11];
    const float* b1    = (const float*)d_in[12];
    const float* w2    = (const float*)d_in[13];
    const float* b2    = (const float*)d_in[14];
    const float* ln2_g = (const float*)d_in[15];
    const float* ln2_b = (const float*)d_in[16];
    float* out = (float*)d_out;

    half *q, *k, *v, *ctx, *xh, *ath, *hh;
    float *y, *attn;
    half *wqh, *wql, *wkh, *wkl, *wvh, *wvl, *woh, *wol, *w1h, *w1l, *w2h, *w2l;
    cudaGetSymbolAddress((void**)&q,   g_q);
    cudaGetSymbolAddress((void**)&k,   g_k);
    cudaGetSymbolAddress((void**)&v,   g_v);
    cudaGetSymbolAddress((void**)&ctx, g_ctx);
    cudaGetSymbolAddress((void**)&xh,  g_xh);
    cudaGetSymbolAddress((void**)&ath, g_ath);
    cudaGetSymbolAddress((void**)&hh,  g_hh);
    cudaGetSymbolAddress((void**)&y,   g_y);
    cudaGetSymbolAddress((void**)&attn, g_attn);
    cudaGetSymbolAddress((void**)&wqh, g_wq_h); cudaGetSymbolAddress((void**)&wql, g_wq_l);
    cudaGetSymbolAddress((void**)&wkh, g_wk_h); cudaGetSymbolAddress((void**)&wkl, g_wk_l);
    cudaGetSymbolAddress((void**)&wvh, g_wv_h); cudaGetSymbolAddress((void**)&wvl, g_wv_l);
    cudaGetSymbolAddress((void**)&woh, g_wo_h); cudaGetSymbolAddress((void**)&wol, g_wo_l);
    cudaGetSymbolAddress((void**)&w1h, g_w1_h); cudaGetSymbolAddress((void**)&w1l, g_w1_l);
    cudaGetSymbolAddress((void**)&w2h, g_w2_h); cudaGetSymbolAddress((void**)&w2l, g_w2_l);

    cudaFuncSetAttribute(gemm_mma<MODE_QKV>,  cudaFuncAttributeMaxDynamicSharedMemorySize, GEMM_SMEM);
    cudaFuncSetAttribute(gemm_mma<MODE_RES>,  cudaFuncAttributeMaxDynamicSharedMemorySize, GEMM_SMEM);
    cudaFuncSetAttribute(gemm_mma<MODE_GELU>, cudaFuncAttributeMaxDynamicSharedMemorySize, GEMM_SMEM);
    cudaFuncSetAttribute(attn_tc,             cudaFuncAttributeMaxDynamicSharedMemorySize, ATT_SMEM);

    // ---- conversions ----
    {
        const int n4 = (NTOK * D_MODEL) / 4;
        cvt_kernel<<<(n4 + 255) / 256, 256>>>((const float4*)x, (half2*)xh, n4);
    }
    split_launch(wq, wqh, wql, D_MODEL * D_MODEL);
    split_launch(wk, wkh, wkl, D_MODEL * D_MODEL);
    split_launch(wv, wvh, wvl, D_MODEL * D_MODEL);
    split_launch(wo, woh, wol, D_MODEL * D_MODEL);
    split_launch(w1, w1h, w1l, DFF * D_MODEL);
    split_launch(w2, w2h, w2l, D_MODEL * DFF);

    const dim3 blk(256);
    const dim3 gD(D_MODEL / 128, NTOK / 128);   // (8, 32)
    const dim3 gF(DFF / 128,     NTOK / 128);   // (32, 32)

    // 1) QKV projections -> f16 [B,H,S,Dk]; Q pre-scaled by 1/8
    gemm_mma<MODE_QKV><<<gD, blk, GEMM_SMEM>>>(xh, wqh, wql, bq, nullptr, nullptr, q,
                                               NTOK, D_MODEL, D_MODEL, 0.125f);
    gemm_mma<MODE_QKV><<<gD, blk, GEMM_SMEM>>>(xh, wkh, wkl, bk, nullptr, nullptr, k,
                                               NTOK, D_MODEL, D_MODEL, 1.0f);
    gemm_mma<MODE_QKV><<<gD, blk, GEMM_SMEM>>>(xh, wvh, wvl, bv, nullptr, nullptr, v,
                                               NTOK, D_MODEL, D_MODEL, 1.0f);

    // 2) flash attention -> ctx f16
    attn_tc<<<dim3(SEQ / 128, 2 * NHEAD), blk, ATT_SMEM>>>(q, k, v, ctx);

    // 3) O projection + residual -> y fp32
    gemm_mma<MODE_RES><<<gD, blk, GEMM_SMEM>>>(ctx, woh, wol, bo, x, y, nullptr,
                                               NTOK, D_MODEL, D_MODEL, 1.0f);

    // 4) LN1 -> attn fp32 + ath f16
    ln_kernel<true><<<NTOK, blk>>>(y, ln1_g, ln1_b, attn, ath);

    // 5) FF1 + GELU -> h f16
    gemm_mma<MODE_GELU><<<gF, blk, GEMM_SMEM>>>(ath, w1h, w1l, b1, nullptr, nullptr, hh,
                                                NTOK, DFF, D_MODEL, 1.0f);

    // 6) FF2 + residual -> y fp32
    gemm_mma<MODE_RES><<<gD, blk, GEMM_SMEM>>>(hh, w2h, w2l, b2, attn, y, nullptr,
                                               NTOK, D_MODEL, DFF, 1.0f);

    // 7) LN2 -> out
    ln_kernel<false><<<NTOK, blk>>>(y, ln2_g, ln2_b, out, nullptr);
}

// round 6
// speedup vs baseline: 12.5056x; 1.7423x over previous
#include <cuda_runtime.h>
#include <cuda_fp16.h>
#include <math.h>
#include <stdint.h>

// ---------------------------------------------------------------------------
// TransformerBlock B=2,S=2048,D=1024,H=16,Dk=64,DFF=4096
// GEMMs: mma.sync f16 single-term (weights + activations f16, fp32 accum).
// QKV fused into one GEMM (N=3072). Tensor-core flash attention.
// ---------------------------------------------------------------------------

#define D_MODEL 1024
#define NTOK    4096
#define NHEAD   16
#define DK      64
#define DFF     4096
#define SEQ     2048
#define EPS     1e-5f

// ------------------------- scratch (static device mem) ---------------------
__device__ half  g_qkv[3 * NTOK * D_MODEL];       // q | k | v, each [B,H,S,Dk]
__device__ half  g_ctx[NTOK * D_MODEL];
__device__ half  g_xh[NTOK * D_MODEL];
__device__ half  g_ath[NTOK * D_MODEL];
__device__ half  g_hh[NTOK * DFF];
__device__ float g_y[NTOK * D_MODEL];
__device__ float g_attn[NTOK * D_MODEL];

__device__ half  g_wqkv[3 * D_MODEL * D_MODEL];   // wq | wk | wv rows
__device__ half  g_wo[D_MODEL * D_MODEL];
__device__ half  g_w1[DFF * D_MODEL];
__device__ half  g_w2[D_MODEL * DFF];
__device__ float g_bqkv[3 * D_MODEL];

// ------------------------------ helpers ------------------------------------
__device__ __forceinline__ uint32_t smem_u32(const void* p) {
    uint32_t a;
    asm("{ .reg .u64 t; cvta.to.shared.u64 t, %1; cvt.u32.u64 %0, t; }" : "=r"(a) : "l"(p));
    return a;
}
#define CP_ASYNC16(dst, src) \
    asm volatile("cp.async.cg.shared.global [%0], [%1], 16;" :: "r"(dst), "l"(src))
#define CP_COMMIT() asm volatile("cp.async.commit_group;")
#define CP_WAIT0()  asm volatile("cp.async.wait_group 0;" ::: "memory")

#define LDMATRIX_X4(r0, r1, r2, r3, a) \
    asm volatile("ldmatrix.sync.aligned.m8n8.x4.shared.b16 {%0,%1,%2,%3}, [%4];" \
                 : "=r"(r0), "=r"(r1), "=r"(r2), "=r"(r3) : "r"(a))
#define LDMATRIX_X4_TRANS(r0, r1, r2, r3, a) \
    asm volatile("ldmatrix.sync.aligned.m8n8.x4.trans.shared.b16 {%0,%1,%2,%3}, [%4];" \
                 : "=r"(r0), "=r"(r1), "=r"(r2), "=r"(r3) : "r"(a))

#define MMA16816(c, a, b) \
    asm volatile("mma.sync.aligned.m16n8k16.row.col.f32.f16.f16.f32 " \
                 "{%0,%1,%2,%3}, {%4,%5,%6,%7}, {%8,%9}, {%0,%1,%2,%3};" \
                 : "+f"((c)[0]), "+f"((c)[1]), "+f"((c)[2]), "+f"((c)[3]) \
                 : "r"((a)[0]), "r"((a)[1]), "r"((a)[2]), "r"((a)[3]), \
                   "r"((b)[0]), "r"((b)[1]))

__device__ __forceinline__ float gelu_f(float x) {
    return 0.5f * x * (1.0f + erff(x * 0.70710678118654752f));
}
__device__ __forceinline__ uint32_t h2pack(float a, float b) {
    half2 h = __floats2half2_rn(a, b);
    return *(uint32_t*)&h;
}

// ------------------------------ MMA GEMM -----------------------------------
// C[M,N] = A_f16[M,K] @ W_f16[N,K]^T  (fp32 accum). BM=BN=128, BK=64.
#define MODE_QKV  1
#define MODE_RES  2
#define MODE_GELU 3

#define ROWB   144               // 64 f16 = 128B data + 16B pad (conflict-free)
#define TILEB  (128 * ROWB)      // 18432
#define STAGEB (2 * TILEB)       // 36864 (A + B)
#define GEMM_SMEM (2 * STAGEB)   // 73728

template <int MODE>
__global__ void __launch_bounds__(256, 2) gemm_mma(
    const half* __restrict__ A, const half* __restrict__ W,
    const float* __restrict__ bias, const float* __restrict__ res,
    float* __restrict__ Cf, half* __restrict__ Ch,
    int M, int N, int K)
{
    extern __shared__ __align__(128) char dsm[];
    const uint32_t sbase = smem_u32(dsm);

    const int tid    = threadIdx.x;
    const int lane   = tid & 31;
    const int warp   = tid >> 5;
    const int warp_m = warp & 3;        // 4 along M -> 32 rows each
    const int warp_n = warp >> 2;       // 2 along N -> 64 cols each
    const int brow   = blockIdx.y * 128;
    const int bcol   = blockIdx.x * 128;

    // cp.async map: per tile, idx = tid + i*256 (i<4): row idx>>3, chunk idx&7
    const half* Ap = A + (size_t)brow * K;
    const half* Wp = W + (size_t)bcol * K;

    // ldmatrix lane addresses
    const int g = lane >> 3, r = lane & 7;
    const uint32_t aoff = (uint32_t)((warp_m * 32 + (g & 1) * 8 + r) * ROWB + (g >> 1) * 16);
    const uint32_t boff = (uint32_t)((warp_n * 64 + (g >> 1) * 8 + r) * ROWB + (g & 1) * 16);

    float acc[2][8][4];
    #pragma unroll
    for (int i = 0; i < 2; i++)
        #pragma unroll
        for (int j = 0; j < 8; j++)
            #pragma unroll
            for (int c = 0; c < 4; c++) acc[i][j][c] = 0.0f;

    const int T = K >> 6;   // BK = 64

    // prologue: stage 0
    #pragma unroll
    for (int i = 0; i < 4; i++) {
        const int idx = tid + i * 256;
        const int row = idx >> 3, c = idx & 7;
        const uint32_t so = (uint32_t)(row * ROWB + c * 16);
        CP_ASYNC16(sbase + so,         Ap + (size_t)row * K + c * 8);
        CP_ASYNC16(sbase + TILEB + so, Wp + (size_t)row * K + c * 8);
    }
    CP_COMMIT();
    CP_WAIT0();
    __syncthreads();

    for (int t = 0; t < T; t++) {
        const uint32_t cur = sbase + (uint32_t)(t & 1) * STAGEB;
        if (t + 1 < T) {
            const int k0 = (t + 1) * 64;
            const uint32_t nxt = sbase + (uint32_t)((t + 1) & 1) * STAGEB;
            #pragma unroll
            for (int i = 0; i < 4; i++) {
                const int idx = tid + i * 256;
                const int row = idx >> 3, c = idx & 7;
                const uint32_t so = (uint32_t)(row * ROWB + c * 16);
                CP_ASYNC16(nxt + so,         Ap + (size_t)row * K + k0 + c * 8);
                CP_ASYNC16(nxt + TILEB + so, Wp + (size_t)row * K + k0 + c * 8);
            }
            CP_COMMIT();
        }

        const uint32_t sA = cur + aoff;
        const uint32_t sB = cur + TILEB + boff;

        #pragma unroll
        for (int ks = 0; ks < 4; ks++) {
            const uint32_t ko = ks * 32;   // 16 f16 = 32B
            uint32_t a[2][4], bb[8][2];

            #pragma unroll
            for (int mi = 0; mi < 2; mi++)
                LDMATRIX_X4(a[mi][0], a[mi][1], a[mi][2], a[mi][3],
                            sA + mi * (16 * ROWB) + ko);
            #pragma unroll
            for (int np = 0; np < 4; np++)
                LDMATRIX_X4(bb[np * 2][0], bb[np * 2][1], bb[np * 2 + 1][0], bb[np * 2 + 1][1],
                            sB + np * (16 * ROWB) + ko);
            #pragma unroll
            for (int mi = 0; mi < 2; mi++)
                #pragma unroll
                for (int ni = 0; ni < 8; ni++)
                    MMA16816(acc[mi][ni], a[mi], bb[ni]);
        }

        if (t + 1 < T) CP_WAIT0();
        __syncthreads();
    }

    // ------------------------------ epilogue -------------------------------
    const int mbase = brow + warp_m * 32 + (lane >> 2);
    const int nbase = bcol + warp_n * 64 + (lane & 3) * 2;

    #pragma unroll
    for (int mi = 0; mi < 2; mi++) {
        #pragma unroll
        for (int half_ = 0; half_ < 2; half_++) {
            const int m = mbase + mi * 16 + half_ * 8;
            #pragma unroll
            for (int ni = 0; ni < 8; ni++) {
                const int n = nbase + ni * 8;
                float vx = acc[mi][ni][half_ * 2 + 0];
                float vy = acc[mi][ni][half_ * 2 + 1];
                const float2 bb2 = *(const float2*)(bias + n);
                vx += bb2.x; vy += bb2.y;
                if (MODE == MODE_RES) {
                    const float2 rr = *(const float2*)(res + (size_t)m * N + n);
                    float2 o; o.x = vx + rr.x; o.y = vy + rr.y;
                    *(float2*)(Cf + (size_t)m * N + n) = o;
                } else if (MODE == MODE_QKV) {
                    // n in [0,3072): which = q/k/v, c = channel
                    const int which = n >> 10;
                    const int c  = n & 1023;
                    const int hq = c >> 6, dq = c & 63;
                    const int bq = m >> 11, sq = m & 2047;
                    const float sc = (which == 0) ? 0.125f : 1.0f;
                    half2 o = __floats2half2_rn(vx * sc, vy * sc);
                    *(half2*)(Ch + (size_t)which * (NTOK * D_MODEL)
                              + ((size_t)(bq * NHEAD + hq) * SEQ + sq) * DK + dq) = o;
                } else {  // GELU
                    half2 o = __floats2half2_rn(gelu_f(vx), gelu_f(vy));
                    *(half2*)(Ch + (size_t)m * N + n) = o;
                }
            }
        }
    }
}

// ----------------------- conversions / packing -----------------------------
__global__ void __launch_bounds__(256) cvt_kernel(
    const float4* __restrict__ src, half2* __restrict__ dst, int n4)
{
    const int i = blockIdx.x * blockDim.x + threadIdx.x;
    if (i >= n4) return;
    float4 v = src[i];
    dst[i * 2 + 0] = __floats2half2_rn(v.x, v.y);
    dst[i * 2 + 1] = __floats2half2_rn(v.z, v.w);
}

__global__ void __launch_bounds__(256) pack_bias_kernel(
    const float* __restrict__ bq, const float* __restrict__ bk,
    const float* __restrict__ bv, float* __restrict__ dst)
{
    const int i = blockIdx.x * blockDim.x + threadIdx.x;
    if (i < D_MODEL)           dst[i] = bq[i];
    else if (i < 2 * D_MODEL)  dst[i] = bk[i - D_MODEL];
    else if (i < 3 * D_MODEL)  dst[i] = bv[i - 2 * D_MODEL];
}

// ---------------------- tensor-core flash attention ------------------------
// Q pre-scaled by 1/8. Q/K/V: [B*H, S, 64] f16. ctx: [B, S, 1024] f16.
#define KROWB 144
#define ATT_SQ_B  (128 * KROWB)              // 18432
#define ATT_KV_B  (64 * KROWB)               // 9216
#define ATT_SMEM  (ATT_SQ_B + 4 * ATT_KV_B)  // 55296

__global__ void __launch_bounds__(256, 2) attn_tc(
    const half* __restrict__ Qg, const half* __restrict__ Kg,
    const half* __restrict__ Vg, half* __restrict__ ctx)
{
    extern __shared__ __align__(128) char sm[];
    const uint32_t sb = smem_u32(sm);
    const uint32_t sQ = sb;
    const uint32_t sKs[2] = { sb + ATT_SQ_B,                sb + ATT_SQ_B + 2 * ATT_KV_B };
    const uint32_t sVs[2] = { sb + ATT_SQ_B + ATT_KV_B,     sb + ATT_SQ_B + 3 * ATT_KV_B };

    const int tid  = threadIdx.x;
    const int lane = tid & 31;
    const int warp = tid >> 5;
    const int bh   = blockIdx.y;
    const int q0   = blockIdx.x * 128;

    const half* Qp = Qg + ((size_t)bh * SEQ + q0) * DK;
    const half* Kp = Kg + (size_t)bh * SEQ * DK;
    const half* Vp = Vg + (size_t)bh * SEQ * DK;

    #pragma unroll
    for (int i = 0; i < 4; i++) {
        const int idx = tid + i * 256;
        const int row = idx >> 3, c = idx & 7;
        CP_ASYNC16(sQ + (uint32_t)(row * KROWB + c * 16), Qp + (size_t)row * DK + c * 8);
    }
    #pragma unroll
    for (int i = 0; i < 2; i++) {
        const int idx = tid + i * 256;
        const int row = idx >> 3, c = idx & 7;
        CP_ASYNC16(sKs[0] + (uint32_t)(row * KROWB + c * 16), Kp + (size_t)row * DK + c * 8);
        CP_ASYNC16(sVs[0] + (uint32_t)(row * KROWB + c * 16), Vp + (size_t)row * DK + c * 8);
    }
    CP_COMMIT(); CP_WAIT0();
    __syncthreads();

    const int g = lane >> 3, r8 = lane & 7;

    uint32_t qa[4][4];
    {
        const uint32_t ao = sQ + (uint32_t)((warp * 16 + (g & 1) * 8 + r8) * KROWB + (g >> 1) * 16);
        #pragma unroll
        for (int kf = 0; kf < 4; kf++)
            LDMATRIX_X4(qa[kf][0], qa[kf][1], qa[kf][2], qa[kf][3], ao + kf * 32);
    }

    float oacc[8][4];
    #pragma unroll
    for (int i = 0; i < 8; i++)
        #pragma unroll
        for (int c = 0; c < 4; c++) oacc[i][c] = 0.0f;
    float mrun0 = -1e30f, mrun1 = -1e30f, lrun0 = 0.0f, lrun1 = 0.0f;

    const uint32_t koff = (uint32_t)(((g >> 1) * 8 + r8) * KROWB + (g & 1) * 16);
    const uint32_t voff = (uint32_t)(((g & 1) * 8 + r8) * KROWB + (g >> 1) * 16);

    for (int kb = 0; kb < SEQ / 64; kb++) {
        if (kb + 1 < SEQ / 64) {
            const uint32_t st = (uint32_t)((kb + 1) & 1);
            const size_t kbase = (size_t)(kb + 1) * 64 * DK;
            #pragma unroll
            for (int i = 0; i < 2; i++) {
                const int idx = tid + i * 256;
                const int row = idx >> 3, c = idx & 7;
                CP_ASYNC16(sKs[st] + (uint32_t)(row * KROWB + c * 16), Kp + kbase + (size_t)row * DK + c * 8);
                CP_ASYNC16(sVs[st] + (uint32_t)(row * KROWB + c * 16), Vp + kbase + (size_t)row * DK + c * 8);
            }
            CP_COMMIT();
        }

        const uint32_t sk = sKs[kb & 1], sv = sVs[kb & 1];

        // ---- S = Q @ K^T ----
        float sf[8][4];
        #pragma unroll
        for (int i = 0; i < 8; i++)
            #pragma unroll
            for (int c = 0; c < 4; c++) sf[i][c] = 0.0f;

        #pragma unroll
        for (int kf = 0; kf < 4; kf++) {
            uint32_t kbv[8][2];
            const uint32_t bo = sk + koff + kf * 32;
            #pragma unroll
            for (int np = 0; np < 4; np++)
                LDMATRIX_X4(kbv[np * 2][0], kbv[np * 2][1], kbv[np * 2 + 1][0], kbv[np * 2 + 1][1],
                            bo + np * (16 * KROWB));
            #pragma unroll
            for (int ni = 0; ni < 8; ni++)
                MMA16816(sf[ni], qa[kf], kbv[ni]);
        }

        // ---- online softmax ----
        float mx0 = -1e30f, mx1 = -1e30f;
        #pragma unroll
        for (int ni = 0; ni < 8; ni++) {
            mx0 = fmaxf(mx0, fmaxf(sf[ni][0], sf[ni][1]));
            mx1 = fmaxf(mx1, fmaxf(sf[ni][2], sf[ni][3]));
        }
        mx0 = fmaxf(mx0, __shfl_xor_sync(0xffffffffu, mx0, 1));
        mx0 = fmaxf(mx0, __shfl_xor_sync(0xffffffffu, mx0, 2));
        mx1 = fmaxf(mx1, __shfl_xor_sync(0xffffffffu, mx1, 1));
        mx1 = fmaxf(mx1, __shfl_xor_sync(0xffffffffu, mx1, 2));

        const float mn0 = fmaxf(mrun0, mx0), mn1 = fmaxf(mrun1, mx1);
        const float cr0 = __expf(mrun0 - mn0), cr1 = __expf(mrun1 - mn1);
        float s0 = 0.0f, s1 = 0.0f;
        #pragma unroll
        for (int ni = 0; ni < 8; ni++) {
            sf[ni][0] = __expf(sf[ni][0] - mn0); s0 += sf[ni][0];
            sf[ni][1] = __expf(sf[ni][1] - mn0); s0 += sf[ni][1];
            sf[ni][2] = __expf(sf[ni][2] - mn1); s1 += sf[ni][2];
            sf[ni][3] = __expf(sf[ni][3] - mn1); s1 += sf[ni][3];
        }
        s0 += __shfl_xor_sync(0xffffffffu, s0, 1);
        s0 += __shfl_xor_sync(0xffffffffu, s0, 2);
        s1 += __shfl_xor_sync(0xffffffffu, s1, 1);
        s1 += __shfl_xor_sync(0xffffffffu, s1, 2);
        lrun0 = lrun0 * cr0 + s0;
        lrun1 = lrun1 * cr1 + s1;
        #pragma unroll
        for (int ni = 0; ni < 8; ni++) {
            oacc[ni][0] *= cr0; oacc[ni][1] *= cr0;
            oacc[ni][2] *= cr1; oacc[ni][3] *= cr1;
        }
        mrun0 = mn0; mrun1 = mn1;

        // ---- O += P @ V ----
        #pragma unroll
        for (int kf = 0; kf < 4; kf++) {
            uint32_t pa[4];
            pa[0] = h2pack(sf[2 * kf][0],     sf[2 * kf][1]);
            pa[1] = h2pack(sf[2 * kf][2],     sf[2 * kf][3]);
            pa[2] = h2pack(sf[2 * kf + 1][0], sf[2 * kf + 1][1]);
            pa[3] = h2pack(sf[2 * kf + 1][2], sf[2 * kf + 1][3]);

            uint32_t vb[8][2];
            const uint32_t vo = sv + voff + kf * (16 * KROWB);
            #pragma unroll
            for (int np = 0; np < 4; np++)
                LDMATRIX_X4_TRANS(vb[np * 2][0], vb[np * 2][1], vb[np * 2 + 1][0], vb[np * 2 + 1][1],
                                  vo + np * 32);
            #pragma unroll
            for (int ni = 0; ni < 8; ni++)
                MMA16816(oacc[ni], pa, vb[ni]);
        }

        if (kb + 1 < SEQ / 64) CP_WAIT0();
        __syncthreads();
    }

    // ---- write ctx ----
    const int b = bh >> 4, h = bh & 15;
    const float i0 = 1.0f / lrun0, i1 = 1.0f / lrun1;
    const int tok = q0 + warp * 16 + (lane >> 2);
    half* p0 = ctx + (size_t)(b * SEQ + tok) * D_MODEL + h * DK + (lane & 3) * 2;
    half* p1 = p0 + 8 * D_MODEL;
    #pragma unroll
    for (int ni = 0; ni < 8; ni++) {
        *(half2*)(p0 + ni * 8) = __floats2half2_rn(oacc[ni][0] * i0, oacc[ni][1] * i0);
        *(half2*)(p1 + ni * 8) = __floats2half2_rn(oacc[ni][2] * i1, oacc[ni][3] * i1);
    }
}

// ------------------------------ LayerNorm ----------------------------------
template <bool HOUT>
__global__ void __launch_bounds__(256) ln_kernel(
    const float* __restrict__ X, const float* __restrict__ G,
    const float* __restrict__ Bb, float* __restrict__ Y, half* __restrict__ Yh)
{
    __shared__ float red[8];
    __shared__ float stat[2];
    const int row = blockIdx.x;
    const int tid = threadIdx.x;
    const int lane = tid & 31, warp = tid >> 5;

    float4 v = *(const float4*)(X + (size_t)row * D_MODEL + tid * 4);

    float s = v.x + v.y + v.z + v.w;
    #pragma unroll
    for (int o = 16; o; o >>= 1) s += __shfl_xor_sync(0xffffffffu, s, o);
    if (lane == 0) red[warp] = s;
    __syncthreads();
    if (tid == 0) {
        float t = 0.0f;
        #pragma unroll
        for (int i = 0; i < 8; i++) t += red[i];
        stat[0] = t * (1.0f / D_MODEL);
    }
    __syncthreads();
    const float mu = stat[0];

    const float d0 = v.x - mu, d1 = v.y - mu, d2 = v.z - mu, d3 = v.w - mu;
    float q = d0 * d0 + d1 * d1 + d2 * d2 + d3 * d3;
    #pragma unroll
    for (int o = 16; o; o >>= 1) q += __shfl_xor_sync(0xffffffffu, q, o);
    if (lane == 0) red[warp] = q;
    __syncthreads();
    if (tid == 0) {
        float t = 0.0f;
        #pragma unroll
        for (int i = 0; i < 8; i++) t += red[i];
        stat[1] = rsqrtf(t * (1.0f / D_MODEL) + EPS);
    }
    __syncthreads();
    const float rstd = stat[1];

    const int c = tid * 4;
    float4 gg = *(const float4*)(G + c);
    float4 bb = *(const float4*)(Bb + c);
    float4 o;
    o.x = d0 * rstd * gg.x + bb.x;
    o.y = d1 * rstd * gg.y + bb.y;
    o.z = d2 * rstd * gg.z + bb.z;
    o.w = d3 * rstd * gg.w + bb.w;
    *(float4*)(Y + (size_t)row * D_MODEL + c) = o;

    if (HOUT) {
        *(half2*)(Yh + (size_t)row * D_MODEL + c)     = __floats2half2_rn(o.x, o.y);
        *(half2*)(Yh + (size_t)row * D_MODEL + c + 2) = __floats2half2_rn(o.z, o.w);
    }
}

// ------------------------------ launch -------------------------------------
static inline void cvt_launch(const float* src, half* dst, int n) {
    const int n4 = n / 4;
    cvt_kernel<<<(n4 + 255) / 256, 256>>>((const float4*)src, (half2*)dst, n4);
}

extern "C" void kernel_launch(void* const* d_in, const int* in_sizes, int n_in,
                              void* d_out, int out_size)
{
    const float* x     = (const float*)d_in[0];
    const float* wq    = (const float*)d_in[1];
    const float* bq    = (const float*)d_in[2];
    const float* wk    = (const float*)d_in[3];
    const float* bk    = (const float*)d_in[4];
    const float* wv    = (const float*)d_in[5];
    const float* bv    = (const float*)d_in[6];
    const float* wo    = (const float*)d_in[7];
    const float* bo    = (const float*)d_in[8];
    const float* ln1_g = (const float*)d_in[9];
    const float* ln1_b = (const float*)d_in[10];
    const float* w1    = (const float*)d_in[11];
    const float* b1    = (const float*)d_in[12];
    const float* w2    = (const float*)d_in[13];
    const float* b2    = (const float*)d_in[14];
    const float* ln2_g = (const float*)d_in[15];
    const float* ln2_b = (const float*)d_in[16];
    float* out = (float*)d_out;

    half *qkv, *ctx, *xh, *ath, *hh, *wqkvh, *woh, *w1h, *w2h;
    float *y, *attn, *bqkv;
    cudaGetSymbolAddress((void**)&qkv,   g_qkv);
    cudaGetSymbolAddress((void**)&ctx,   g_ctx);
    cudaGetSymbolAddress((void**)&xh,    g_xh);
    cudaGetSymbolAddress((void**)&ath,   g_ath);
    cudaGetSymbolAddress((void**)&hh,    g_hh);
    cudaGetSymbolAddress((void**)&y,     g_y);
    cudaGetSymbolAddress((void**)&attn,  g_attn);
    cudaGetSymbolAddress((void**)&wqkvh, g_wqkv);
    cudaGetSymbolAddress((void**)&woh,   g_wo);
    cudaGetSymbolAddress((void**)&w1h,   g_w1);
    cudaGetSymbolAddress((void**)&w2h,   g_w2);
    cudaGetSymbolAddress((void**)&bqkv,  g_bqkv);

    cudaFuncSetAttribute(gemm_mma<MODE_QKV>,  cudaFuncAttributeMaxDynamicSharedMemorySize, GEMM_SMEM);
    cudaFuncSetAttribute(gemm_mma<MODE_RES>,  cudaFuncAttributeMaxDynamicSharedMemorySize, GEMM_SMEM);
    cudaFuncSetAttribute(gemm_mma<MODE_GELU>, cudaFuncAttributeMaxDynamicSharedMemorySize, GEMM_SMEM);
    cudaFuncSetAttribute(attn_tc,             cudaFuncAttributeMaxDynamicSharedMemorySize, ATT_SMEM);

    // ---- conversions / packing ----
    cvt_launch(x,  xh, NTOK * D_MODEL);
    cvt_launch(wq, wqkvh,                           D_MODEL * D_MODEL);
    cvt_launch(wk, wqkvh + 1 * D_MODEL * D_MODEL,   D_MODEL * D_MODEL);
    cvt_launch(wv, wqkvh + 2 * D_MODEL * D_MODEL,   D_MODEL * D_MODEL);
    cvt_launch(wo, woh, D_MODEL * D_MODEL);
    cvt_launch(w1, w1h, DFF * D_MODEL);
    cvt_launch(w2, w2h, D_MODEL * DFF);
    pack_bias_kernel<<<12, 256>>>(bq, bk, bv, bqkv);

    const dim3 blk(256);
    const dim3 gQ(3 * D_MODEL / 128, NTOK / 128);   // (24, 32)
    const dim3 gD(D_MODEL / 128,     NTOK / 128);   // (8, 32)
    const dim3 gF(DFF / 128,         NTOK / 128);   // (32, 32)

    // 1) fused QKV projection -> f16 [3][B,H,S,Dk]; Q pre-scaled by 1/8
    gemm_mma<MODE_QKV><<<gQ, blk, GEMM_SMEM>>>(xh, wqkvh, bqkv, nullptr, nullptr, qkv,
                                               NTOK, 3 * D_MODEL, D_MODEL);

    // 2) flash attention -> ctx f16
    attn_tc<<<dim3(SEQ / 128, 2 * NHEAD), blk, ATT_SMEM>>>(
        qkv, qkv + (size_t)NTOK * D_MODEL, qkv + 2 * (size_t)NTOK * D_MODEL, ctx);

    // 3) O projection + residual -> y fp32
    gemm_mma<MODE_RES><<<gD, blk, GEMM_SMEM>>>(ctx, woh, bo, x, y, nullptr,
                                               NTOK, D_MODEL, D_MODEL);

    // 4) LN1 -> attn fp32 + ath f16
    ln_kernel<true><<<NTOK, blk>>>(y, ln1_g, ln1_b, attn, ath);

    // 5) FF1 + GELU -> h f16
    gemm_mma<MODE_GELU><<<gF, blk, GEMM_SMEM>>>(ath, w1h, b1, nullptr, nullptr, hh,
                                                NTOK, DFF, D_MODEL);

    // 6) FF2 + residual -> y fp32
    gemm_mma<MODE_RES><<<gD, blk, GEMM_SMEM>>>(hh, w2h, b2, attn, y, nullptr,
                                               NTOK, D_MODEL, DFF);

    // 7) LN2 -> out
    ln_kernel<false><<<NTOK, blk>>>(y, ln2_g, ln2_b, out, nullptr);
}

// round 7
// speedup vs baseline: 12.7950x; 1.0231x over previous
#include <cuda_runtime.h>
#include <cuda_fp16.h>
#include <math.h>
#include <stdint.h>

// ---------------------------------------------------------------------------
// TransformerBlock B=2,S=2048,D=1024,H=16,Dk=64,DFF=4096
// GEMMs: mma.sync f16 single-term, fused QKV, 3-stage cp.async pipelines.
// Fused one-shot conversion kernel. Tensor-core flash attention.
// ---------------------------------------------------------------------------

#define D_MODEL 1024
#define NTOK    4096
#define NHEAD   16
#define DK      64
#define DFF     4096
#define SEQ     2048
#define EPS     1e-5f

// ------------------------- scratch (static device mem) ---------------------
__device__ half  g_qkv[3 * NTOK * D_MODEL];       // q | k | v, each [B,H,S,Dk]
__device__ half  g_ctx[NTOK * D_MODEL];
__device__ half  g_xh[NTOK * D_MODEL];
__device__ half  g_ath[NTOK * D_MODEL];
__device__ half  g_hh[NTOK * DFF];
__device__ float g_y[NTOK * D_MODEL];
__device__ float g_attn[NTOK * D_MODEL];

__device__ half  g_wqkv[3 * D_MODEL * D_MODEL];   // wq | wk | wv rows
__device__ half  g_wo[D_MODEL * D_MODEL];
__device__ half  g_w1[DFF * D_MODEL];
__device__ half  g_w2[D_MODEL * DFF];
__device__ float g_bqkv[3 * D_MODEL];

// ------------------------------ helpers ------------------------------------
__device__ __forceinline__ uint32_t smem_u32(const void* p) {
    uint32_t a;
    asm("{ .reg .u64 t; cvta.to.shared.u64 t, %1; cvt.u32.u64 %0, t; }" : "=r"(a) : "l"(p));
    return a;
}
#define CP_ASYNC16(dst, src) \
    asm volatile("cp.async.cg.shared.global [%0], [%1], 16;" :: "r"(dst), "l"(src))
#define CP_COMMIT() asm volatile("cp.async.commit_group;")
#define CP_WAIT0()  asm volatile("cp.async.wait_group 0;" ::: "memory")
#define CP_WAIT1()  asm volatile("cp.async.wait_group 1;" ::: "memory")

#define LDMATRIX_X4(r0, r1, r2, r3, a) \
    asm volatile("ldmatrix.sync.aligned.m8n8.x4.shared.b16 {%0,%1,%2,%3}, [%4];" \
                 : "=r"(r0), "=r"(r1), "=r"(r2), "=r"(r3) : "r"(a))
#define LDMATRIX_X4_TRANS(r0, r1, r2, r3, a) \
    asm volatile("ldmatrix.sync.aligned.m8n8.x4.trans.shared.b16 {%0,%1,%2,%3}, [%4];" \
                 : "=r"(r0), "=r"(r1), "=r"(r2), "=r"(r3) : "r"(a))

#define MMA16816(c, a, b) \
    asm volatile("mma.sync.aligned.m16n8k16.row.col.f32.f16.f16.f32 " \
                 "{%0,%1,%2,%3}, {%4,%5,%6,%7}, {%8,%9}, {%0,%1,%2,%3};" \
                 : "+f"((c)[0]), "+f"((c)[1]), "+f"((c)[2]), "+f"((c)[3]) \
                 : "r"((a)[0]), "r"((a)[1]), "r"((a)[2]), "r"((a)[3]), \
                   "r"((b)[0]), "r"((b)[1]))

__device__ __forceinline__ float gelu_f(float x) {
    return 0.5f * x * (1.0f + erff(x * 0.70710678118654752f));
}
__device__ __forceinline__ uint32_t h2pack(float a, float b) {
    half2 h = __floats2half2_rn(a, b);
    return *(uint32_t*)&h;
}

// ------------------------------ MMA GEMM -----------------------------------
// C[M,N] = A_f16[M,K] @ W_f16[N,K]^T  (fp32 accum). BM=BN=128, BK=64, 3-stage.
#define MODE_QKV  1
#define MODE_RES  2
#define MODE_GELU 3

#define ROWB   144               // 64 f16 = 128B data + 16B pad (conflict-free)
#define TILEB  (128 * ROWB)      // 18432
#define STAGEB (2 * TILEB)       // 36864 (A + B)
#define GEMM_SMEM (3 * STAGEB)   // 110592

template <int MODE>
__global__ void __launch_bounds__(256, 2) gemm_mma(
    const half* __restrict__ A, const half* __restrict__ W,
    const float* __restrict__ bias, const float* __restrict__ res,
    float* __restrict__ Cf, half* __restrict__ Ch,
    int M, int N, int K)
{
    extern __shared__ __align__(128) char dsm[];
    const uint32_t sbase = smem_u32(dsm);

    const int tid    = threadIdx.x;
    const int lane   = tid & 31;
    const int warp   = tid >> 5;
    const int warp_m = warp & 3;        // 4 along M -> 32 rows each
    const int warp_n = warp >> 2;       // 2 along N -> 64 cols each
    const int brow   = blockIdx.y * 128;
    const int bcol   = blockIdx.x * 128;

    const half* Ap = A + (size_t)brow * K;
    const half* Wp = W + (size_t)bcol * K;

    // ldmatrix lane addresses
    const int g = lane >> 3, r = lane & 7;
    const uint32_t aoff = (uint32_t)((warp_m * 32 + (g & 1) * 8 + r) * ROWB + (g >> 1) * 16);
    const uint32_t boff = (uint32_t)((warp_n * 64 + (g >> 1) * 8 + r) * ROWB + (g & 1) * 16);

    float acc[2][8][4];
    #pragma unroll
    for (int i = 0; i < 2; i++)
        #pragma unroll
        for (int j = 0; j < 8; j++)
            #pragma unroll
            for (int c = 0; c < 4; c++) acc[i][j][c] = 0.0f;

    const int T = K >> 6;   // BK = 64 (T >= 16 here)

    // prologue: issue stages 0 and 1 as two commit groups
    #pragma unroll
    for (int s = 0; s < 2; s++) {
        const uint32_t st = sbase + (uint32_t)s * STAGEB;
        const int k0 = s * 64;
        #pragma unroll
        for (int i = 0; i < 4; i++) {
            const int idx = tid + i * 256;
            const int row = idx >> 3, c = idx & 7;
            const uint32_t so = (uint32_t)(row * ROWB + c * 16);
            CP_ASYNC16(st + so,         Ap + (size_t)row * K + k0 + c * 8);
            CP_ASYNC16(st + TILEB + so, Wp + (size_t)row * K + k0 + c * 8);
        }
        CP_COMMIT();
    }

    int stage = 0;
    for (int t = 0; t < T; t++) {
        if (t == T - 1) CP_WAIT0(); else CP_WAIT1();
        __syncthreads();

        const uint32_t cur = sbase + (uint32_t)stage * STAGEB;

        if (t + 2 < T) {
            const int k0 = (t + 2) * 64;
            int ns = stage + 2; if (ns >= 3) ns -= 3;
            const uint32_t nxt = sbase + (uint32_t)ns * STAGEB;
            #pragma unroll
            for (int i = 0; i < 4; i++) {
                const int idx = tid + i * 256;
                const int row = idx >> 3, c = idx & 7;
                const uint32_t so = (uint32_t)(row * ROWB + c * 16);
                CP_ASYNC16(nxt + so,         Ap + (size_t)row * K + k0 + c * 8);
                CP_ASYNC16(nxt + TILEB + so, Wp + (size_t)row * K + k0 + c * 8);
            }
            CP_COMMIT();
        }

        const uint32_t sA = cur + aoff;
        const uint32_t sB = cur + TILEB + boff;

        #pragma unroll
        for (int ks = 0; ks < 4; ks++) {
            const uint32_t ko = ks * 32;   // 16 f16 = 32B
            uint32_t a[2][4], bb[8][2];

            #pragma unroll
            for (int mi = 0; mi < 2; mi++)
                LDMATRIX_X4(a[mi][0], a[mi][1], a[mi][2], a[mi][3],
                            sA + mi * (16 * ROWB) + ko);
            #pragma unroll
            for (int np = 0; np < 4; np++)
                LDMATRIX_X4(bb[np * 2][0], bb[np * 2][1], bb[np * 2 + 1][0], bb[np * 2 + 1][1],
                            sB + np * (16 * ROWB) + ko);
            #pragma unroll
            for (int mi = 0; mi < 2; mi++)
                #pragma unroll
                for (int ni = 0; ni < 8; ni++)
                    MMA16816(acc[mi][ni], a[mi], bb[ni]);
        }

        if (++stage == 3) stage = 0;
    }

    // ------------------------------ epilogue -------------------------------
    const int mbase = brow + warp_m * 32 + (lane >> 2);
    const int nbase = bcol + warp_n * 64 + (lane & 3) * 2;

    #pragma unroll
    for (int mi = 0; mi < 2; mi++) {
        #pragma unroll
        for (int half_ = 0; half_ < 2; half_++) {
            const int m = mbase + mi * 16 + half_ * 8;
            #pragma unroll
            for (int ni = 0; ni < 8; ni++) {
                const int n = nbase + ni * 8;
                float vx = acc[mi][ni][half_ * 2 + 0];
                float vy = acc[mi][ni][half_ * 2 + 1];
                const float2 bb2 = *(const float2*)(bias + n);
                vx += bb2.x; vy += bb2.y;
                if (MODE == MODE_RES) {
                    const float2 rr = *(const float2*)(res + (size_t)m * N + n);
                    float2 o; o.x = vx + rr.x; o.y = vy + rr.y;
                    *(float2*)(Cf + (size_t)m * N + n) = o;
                } else if (MODE == MODE_QKV) {
                    const int which = n >> 10;
                    const int c  = n & 1023;
                    const int hq = c >> 6, dq = c & 63;
                    const int bq = m >> 11, sq = m & 2047;
                    const float sc = (which == 0) ? 0.125f : 1.0f;
                    half2 o = __floats2half2_rn(vx * sc, vy * sc);
                    *(half2*)(Ch + (size_t)which * (NTOK * D_MODEL)
                              + ((size_t)(bq * NHEAD + hq) * SEQ + sq) * DK + dq) = o;
                } else {  // GELU
                    half2 o = __floats2half2_rn(gelu_f(vx), gelu_f(vy));
                    *(half2*)(Ch + (size_t)m * N + n) = o;
                }
            }
        }
    }
}

// ---------------- fused conversion kernel (all weights + x + bias) ---------
// Unit = 8 floats: read 2x float4 (32B), write 1x uint4 (16B of halfs).
#define U_X   524288u                 // 4M elems
#define U_W   131072u                 // 1M elems
#define B0    (U_X)
#define B1    (B0 + U_W)              // wq end
#define B2    (B1 + U_W)              // wk end
#define B3    (B2 + U_W)              // wv end
#define B4    (B3 + U_W)              // wo end
#define B5    (B4 + U_X)              // w1 end
#define B6    (B5 + U_X)              // w2 end (total units)

__global__ void __launch_bounds__(256) cvt_all(
    const float* __restrict__ x,
    const float* __restrict__ wq, const float* __restrict__ wk,
    const float* __restrict__ wv, const float* __restrict__ wo,
    const float* __restrict__ w1, const float* __restrict__ w2,
    const float* __restrict__ bq, const float* __restrict__ bk,
    const float* __restrict__ bv,
    half* __restrict__ xh, half* __restrict__ wqkvh, half* __restrict__ woh,
    half* __restrict__ w1h, half* __restrict__ w2h, float* __restrict__ bqkv)
{
    const uint32_t gtid = blockIdx.x * blockDim.x + threadIdx.x;
    const uint32_t gstride = gridDim.x * blockDim.x;

    // bias pack: 3*1024 floats = 768 float4
    if (gtid < 768) {
        float4 v = (gtid < 256) ? ((const float4*)bq)[gtid]
                 : (gtid < 512) ? ((const float4*)bk)[gtid - 256]
                                : ((const float4*)bv)[gtid - 512];
        ((float4*)bqkv)[gtid] = v;
    }

    for (uint32_t u = gtid; u < B6; u += gstride) {
        const float* src; half* dst; uint32_t off;
        if (u < B0)      { src = x;  dst = xh;                off = u; }
        else if (u < B1) { src = wq; dst = wqkvh;             off = u - B0; }
        else if (u < B2) { src = wk; dst = wqkvh + 1048576;   off = u - B1; }
        else if (u < B3) { src = wv; dst = wqkvh + 2097152;   off = u - B2; }
        else if (u < B4) { src = wo; dst = woh;               off = u - B3; }
        else if (u < B5) { src = w1; dst = w1h;               off = u - B4; }
        else             { src = w2; dst = w2h;               off = u - B5; }

        const float4 v0 = ((const float4*)src)[off * 2 + 0];
        const float4 v1 = ((const float4*)src)[off * 2 + 1];
        uint4 o;
        o.x = h2pack(v0.x, v0.y);
        o.y = h2pack(v0.z, v0.w);
        o.z = h2pack(v1.x, v1.y);
        o.w = h2pack(v1.z, v1.w);
        ((uint4*)dst)[off] = o;
    }
}

// ---------------------- tensor-core flash attention ------------------------
// Q pre-scaled by 1/8. Q/K/V: [B*H, S, 64] f16. ctx: [B, S, 1024] f16.
// 3-stage K/V pipeline, 64-key blocks, 8 warps x 16 q-rows.
#define KROWB 144
#define ATT_SQ_B  (128 * KROWB)              // 18432
#define ATT_KV_B  (64 * KROWB)               // 9216
#define ATT_SMEM  (ATT_SQ_B + 6 * ATT_KV_B)  // 73728
#define NKB       (SEQ / 64)                 // 32

__global__ void __launch_bounds__(256, 2) attn_tc(
    const half* __restrict__ Qg, const half* __restrict__ Kg,
    const half* __restrict__ Vg, half* __restrict__ ctx)
{
    extern __shared__ __align__(128) char sm[];
    const uint32_t sb = smem_u32(sm);
    const uint32_t sQ = sb;

    const int tid  = threadIdx.x;
    const int lane = tid & 31;
    const int warp = tid >> 5;
    const int bh   = blockIdx.y;
    const int q0   = blockIdx.x * 128;

    const half* Qp = Qg + ((size_t)bh * SEQ + q0) * DK;
    const half* Kp = Kg + (size_t)bh * SEQ * DK;
    const half* Vp = Vg + (size_t)bh * SEQ * DK;

    // prologue: group0 = Q + KV block 0; group1 = KV block 1
    #pragma unroll
    for (int i = 0; i < 4; i++) {
        const int idx = tid + i * 256;
        const int row = idx >> 3, c = idx & 7;
        CP_ASYNC16(sQ + (uint32_t)(row * KROWB + c * 16), Qp + (size_t)row * DK + c * 8);
    }
    {
        const uint32_t sk = sb + ATT_SQ_B, sv = sk + ATT_KV_B;
        #pragma unroll
        for (int i = 0; i < 2; i++) {
            const int idx = tid + i * 256;
            const int row = idx >> 3, c = idx & 7;
            CP_ASYNC16(sk + (uint32_t)(row * KROWB + c * 16), Kp + (size_t)row * DK + c * 8);
            CP_ASYNC16(sv + (uint32_t)(row * KROWB + c * 16), Vp + (size_t)row * DK + c * 8);
        }
    }
    CP_COMMIT();
    {
        const uint32_t sk = sb + ATT_SQ_B + 2 * ATT_KV_B, sv = sk + ATT_KV_B;
        const size_t kbase = (size_t)64 * DK;
        #pragma unroll
        for (int i = 0; i < 2; i++) {
            const int idx = tid + i * 256;
            const int row = idx >> 3, c = idx & 7;
            CP_ASYNC16(sk + (uint32_t)(row * KROWB + c * 16), Kp + kbase + (size_t)row * DK + c * 8);
            CP_ASYNC16(sv + (uint32_t)(row * KROWB + c * 16), Vp + kbase + (size_t)row * DK + c * 8);
        }
    }
    CP_COMMIT();

    const int g = lane >> 3, r8 = lane & 7;

    // wait for group0 (Q + KV0), then load Q fragments
    CP_WAIT1();
    __syncthreads();

    uint32_t qa[4][4];
    {
        const uint32_t ao = sQ + (uint32_t)((warp * 16 + (g & 1) * 8 + r8) * KROWB + (g >> 1) * 16);
        #pragma unroll
        for (int kf = 0; kf < 4; kf++)
            LDMATRIX_X4(qa[kf][0], qa[kf][1], qa[kf][2], qa[kf][3], ao + kf * 32);
    }

    float oacc[8][4];
    #pragma unroll
    for (int i = 0; i < 8; i++)
        #pragma unroll
        for (int c = 0; c < 4; c++) oacc[i][c] = 0.0f;
    float mrun0 = -1e30f, mrun1 = -1e30f, lrun0 = 0.0f, lrun1 = 0.0f;

    const uint32_t koff = (uint32_t)(((g >> 1) * 8 + r8) * KROWB + (g & 1) * 16);
    const uint32_t voff = (uint32_t)(((g & 1) * 8 + r8) * KROWB + (g >> 1) * 16);

    int stage = 0;
    for (int kb = 0; kb < NKB; kb++) {
        if (kb == NKB - 1) CP_WAIT0(); else CP_WAIT1();
        __syncthreads();

        const uint32_t sk = sb + ATT_SQ_B + (uint32_t)stage * (2 * ATT_KV_B);
        const uint32_t sv = sk + ATT_KV_B;

        if (kb + 2 < NKB) {
            int ns = stage + 2; if (ns >= 3) ns -= 3;
            const uint32_t nk = sb + ATT_SQ_B + (uint32_t)ns * (2 * ATT_KV_B);
            const uint32_t nv = nk + ATT_KV_B;
            const size_t kbase = (size_t)(kb + 2) * 64 * DK;
            #pragma unroll
            for (int i = 0; i < 2; i++) {
                const int idx = tid + i * 256;
                const int row = idx >> 3, c = idx & 7;
                CP_ASYNC16(nk + (uint32_t)(row * KROWB + c * 16), Kp + kbase + (size_t)row * DK + c * 8);
                CP_ASYNC16(nv + (uint32_t)(row * KROWB + c * 16), Vp + kbase + (size_t)row * DK + c * 8);
            }
            CP_COMMIT();
        }

        // ---- S = Q @ K^T ----
        float sf[8][4];
        #pragma unroll
        for (int i = 0; i < 8; i++)
            #pragma unroll
            for (int c = 0; c < 4; c++) sf[i][c] = 0.0f;

        #pragma unroll
        for (int kf = 0; kf < 4; kf++) {
            uint32_t kbv[8][2];
            const uint32_t bo = sk + koff + kf * 32;
            #pragma unroll
            for (int np = 0; np < 4; np++)
                LDMATRIX_X4(kbv[np * 2][0], kbv[np * 2][1], kbv[np * 2 + 1][0], kbv[np * 2 + 1][1],
                            bo + np * (16 * KROWB));
            #pragma unroll
            for (int ni = 0; ni < 8; ni++)
                MMA16816(sf[ni], qa[kf], kbv[ni]);
        }

        // ---- online softmax ----
        float mx0 = -1e30f, mx1 = -1e30f;
        #pragma unroll
        for (int ni = 0; ni < 8; ni++) {
            mx0 = fmaxf(mx0, fmaxf(sf[ni][0], sf[ni][1]));
            mx1 = fmaxf(mx1, fmaxf(sf[ni][2], sf[ni][3]));
        }
        mx0 = fmaxf(mx0, __shfl_xor_sync(0xffffffffu, mx0, 1));
        mx0 = fmaxf(mx0, __shfl_xor_sync(0xffffffffu, mx0, 2));
        mx1 = fmaxf(mx1, __shfl_xor_sync(0xffffffffu, mx1, 1));
        mx1 = fmaxf(mx1, __shfl_xor_sync(0xffffffffu, mx1, 2));

        const float mn0 = fmaxf(mrun0, mx0), mn1 = fmaxf(mrun1, mx1);
        const float cr0 = __expf(mrun0 - mn0), cr1 = __expf(mrun1 - mn1);
        float s0 = 0.0f, s1 = 0.0f;
        #pragma unroll
        for (int ni = 0; ni < 8; ni++) {
            sf[ni][0] = __expf(sf[ni][0] - mn0); s0 += sf[ni][0];
            sf[ni][1] = __expf(sf[ni][1] - mn0); s0 += sf[ni][1];
            sf[ni][2] = __expf(sf[ni][2] - mn1); s1 += sf[ni][2];
            sf[ni][3] = __expf(sf[ni][3] - mn1); s1 += sf[ni][3];
        }
        s0 += __shfl_xor_sync(0xffffffffu, s0, 1);
        s0 += __shfl_xor_sync(0xffffffffu, s0, 2);
        s1 += __shfl_xor_sync(0xffffffffu, s1, 1);
        s1 += __shfl_xor_sync(0xffffffffu, s1, 2);
        lrun0 = lrun0 * cr0 + s0;
        lrun1 = lrun1 * cr1 + s1;
        #pragma unroll
        for (int ni = 0; ni < 8; ni++) {
            oacc[ni][0] *= cr0; oacc[ni][1] *= cr0;
            oacc[ni][2] *= cr1; oacc[ni][3] *= cr1;
        }
        mrun0 = mn0; mrun1 = mn1;

        // ---- O += P @ V ----
        #pragma unroll
        for (int kf = 0; kf < 4; kf++) {
            uint32_t pa[4];
            pa[0] = h2pack(sf[2 * kf][0],     sf[2 * kf][1]);
            pa[1] = h2pack(sf[2 * kf][2],     sf[2 * kf][3]);
            pa[2] = h2pack(sf[2 * kf + 1][0], sf[2 * kf + 1][1]);
            pa[3] = h2pack(sf[2 * kf + 1][2], sf[2 * kf + 1][3]);

            uint32_t vb[8][2];
            const uint32_t vo = sv + voff + kf * (16 * KROWB);
            #pragma unroll
            for (int np = 0; np < 4; np++)
                LDMATRIX_X4_TRANS(vb[np * 2][0], vb[np * 2][1], vb[np * 2 + 1][0], vb[np * 2 + 1][1],
                                  vo + np * 32);
            #pragma unroll
            for (int ni = 0; ni < 8; ni++)
                MMA16816(oacc[ni], pa, vb[ni]);
        }

        if (++stage == 3) stage = 0;
    }

    // ---- write ctx ----
    const int b = bh >> 4, h = bh & 15;
    const float i0 = 1.0f / lrun0, i1 = 1.0f / lrun1;
    const int tok = q0 + warp * 16 + (lane >> 2);
    half* p0 = ctx + (size_t)(b * SEQ + tok) * D_MODEL + h * DK + (lane & 3) * 2;
    half* p1 = p0 + 8 * D_MODEL;
    #pragma unroll
    for (int ni = 0; ni < 8; ni++) {
        *(half2*)(p0 + ni * 8) = __floats2half2_rn(oacc[ni][0] * i0, oacc[ni][1] * i0);
        *(half2*)(p1 + ni * 8) = __floats2half2_rn(oacc[ni][2] * i1, oacc[ni][3] * i1);
    }
}

// ------------------------------ LayerNorm ----------------------------------
template <bool HOUT>
__global__ void __launch_bounds__(256) ln_kernel(
    const float* __restrict__ X, const float* __restrict__ G,
    const float* __restrict__ Bb, float* __restrict__ Y, half* __restrict__ Yh)
{
    __shared__ float red[8];
    __shared__ float stat[2];
    const int row = blockIdx.x;
    const int tid = threadIdx.x;
    const int lane = tid & 31, warp = tid >> 5;

    float4 v = *(const float4*)(X + (size_t)row * D_MODEL + tid * 4);

    float s = v.x + v.y + v.z + v.w;
    #pragma unroll
    for (int o = 16; o; o >>= 1) s += __shfl_xor_sync(0xffffffffu, s, o);
    if (lane == 0) red[warp] = s;
    __syncthreads();
    if (tid == 0) {
        float t = 0.0f;
        #pragma unroll
        for (int i = 0; i < 8; i++) t += red[i];
        stat[0] = t * (1.0f / D_MODEL);
    }
    __syncthreads();
    const float mu = stat[0];

    const float d0 = v.x - mu, d1 = v.y - mu, d2 = v.z - mu, d3 = v.w - mu;
    float q = d0 * d0 + d1 * d1 + d2 * d2 + d3 * d3;
    #pragma unroll
    for (int o = 16; o; o >>= 1) q += __shfl_xor_sync(0xffffffffu, q, o);
    if (lane == 0) red[warp] = q;
    __syncthreads();
    if (tid == 0) {
        float t = 0.0f;
        #pragma unroll
        for (int i = 0; i < 8; i++) t += red[i];
        stat[1] = rsqrtf(t * (1.0f / D_MODEL) + EPS);
    }
    __syncthreads();
    const float rstd = stat[1];

    const int c = tid * 4;
    float4 gg = *(const float4*)(G + c);
    float4 bb = *(const float4*)(Bb + c);
    float4 o;
    o.x = d0 * rstd * gg.x + bb.x;
    o.y = d1 * rstd * gg.y + bb.y;
    o.z = d2 * rstd * gg.z + bb.z;
    o.w = d3 * rstd * gg.w + bb.w;
    *(float4*)(Y + (size_t)row * D_MODEL + c) = o;

    if (HOUT) {
        *(half2*)(Yh + (size_t)row * D_MODEL + c)     = __floats2half2_rn(o.x, o.y);
        *(half2*)(Yh + (size_t)row * D_MODEL + c + 2) = __floats2half2_rn(o.z, o.w);
    }
}

// ------------------------------ launch -------------------------------------
extern "C" void kernel_launch(void* const* d_in, const int* in_sizes, int n_in,
                              void* d_out, int out_size)
{
    const float* x     = (const float*)d_in[0];
    const float* wq    = (const float*)d_in[1];
    const float* bq    = (const float*)d_in[2];
    const float* wk    = (const float*)d_in[3];
    const float* bk    = (const float*)d_in[4];
    const float* wv    = (const float*)d_in[5];
    const float* bv    = (const float*)d_in[6];
    const float* wo    = (const float*)d_in[7];
    const float* bo    = (const float*)d_in[8];
    const float* ln1_g = (const float*)d_in[9];
    const float* ln1_b = (const float*)d_in[10];
    const float* w1    = (const float*)d_in[11];
    const float* b1    = (const float*)d_in[12];
    const float* w2    = (const float*)d_in[13];
    const float* b2    = (const float*)d_in[14];
    const float* ln2_g = (const float*)d_in[15];
    const float* ln2_b = (const float*)d_in[16];
    float* out = (float*)d_out;

    half *qkv, *ctx, *xh, *ath, *hh, *wqkvh, *woh, *w1h, *w2h;
    float *y, *attn, *bqkv;
    cudaGetSymbolAddress((void**)&qkv,   g_qkv);
    cudaGetSymbolAddress((void**)&ctx,   g_ctx);
    cudaGetSymbolAddress((void**)&xh,    g_xh);
    cudaGetSymbolAddress((void**)&ath,   g_ath);
    cudaGetSymbolAddress((void**)&hh,    g_hh);
    cudaGetSymbolAddress((void**)&y,     g_y);
    cudaGetSymbolAddress((void**)&attn,  g_attn);
    cudaGetSymbolAddress((void**)&wqkvh, g_wqkv);
    cudaGetSymbolAddress((void**)&woh,   g_wo);
    cudaGetSymbolAddress((void**)&w1h,   g_w1);
    cudaGetSymbolAddress((void**)&w2h,   g_w2);
    cudaGetSymbolAddress((void**)&bqkv,  g_bqkv);

    cudaFuncSetAttribute(gemm_mma<MODE_QKV>,  cudaFuncAttributeMaxDynamicSharedMemorySize, GEMM_SMEM);
    cudaFuncSetAttribute(gemm_mma<MODE_RES>,  cudaFuncAttributeMaxDynamicSharedMemorySize, GEMM_SMEM);
    cudaFuncSetAttribute(gemm_mma<MODE_GELU>, cudaFuncAttributeMaxDynamicSharedMemorySize, GEMM_SMEM);
    cudaFuncSetAttribute(attn_tc,             cudaFuncAttributeMaxDynamicSharedMemorySize, ATT_SMEM);

    // 0) one-shot conversion of x + all weights + bias pack
    cvt_all<<<2048, 256>>>(x, wq, wk, wv, wo, w1, w2, bq, bk, bv,
                           xh, wqkvh, woh, w1h, w2h, bqkv);

    const dim3 blk(256);
    const dim3 gQ(3 * D_MODEL / 128, NTOK / 128);   // (24, 32)
    const dim3 gD(D_MODEL / 128,     NTOK / 128);   // (8, 32)
    const dim3 gF(DFF / 128,         NTOK / 128);   // (32, 32)

    // 1) fused QKV projection -> f16 [3][B,H,S,Dk]; Q pre-scaled by 1/8
    gemm_mma<MODE_QKV><<<gQ, blk, GEMM_SMEM>>>(xh, wqkvh, bqkv, nullptr, nullptr, qkv,
                                               NTOK, 3 * D_MODEL, D_MODEL);

    // 2) flash attention -> ctx f16
    attn_tc<<<dim3(SEQ / 128, 2 * NHEAD), blk, ATT_SMEM>>>(
        qkv, qkv + (size_t)NTOK * D_MODEL, qkv + 2 * (size_t)NTOK * D_MODEL, ctx);

    // 3) O projection + residual -> y fp32
    gemm_mma<MODE_RES><<<gD, blk, GEMM_SMEM>>>(ctx, woh, bo, x, y, nullptr,
                                               NTOK, D_MODEL, D_MODEL);

    // 4) LN1 -> attn fp32 + ath f16
    ln_kernel<true><<<NTOK, blk>>>(y, ln1_g, ln1_b, attn, ath);

    // 5) FF1 + GELU -> h f16
    gemm_mma<MODE_GELU><<<gF, blk, GEMM_SMEM>>>(ath, w1h, b1, nullptr, nullptr, hh,
                                                NTOK, DFF, D_MODEL);

    // 6) FF2 + residual -> y fp32
    gemm_mma<MODE_RES><<<gD, blk, GEMM_SMEM>>>(hh, w2h, b2, attn, y, nullptr,
                                               NTOK, D_MODEL, DFF);

    // 7) LN2 -> out
    ln_kernel<false><<<NTOK, blk>>>(y, ln2_g, ln2_b, out, nullptr);
}